// round 6
// baseline (speedup 1.0000x reference)
#include <cuda_runtime.h>
#include <stdint.h>
#include <math.h>

// Problem constants (fixed shapes)
#define NCELLS 131072
#define IN_D   64
#define HID_D  128
#define OUT_D  64

#define MT   64            // cells per block in main kernel
#define TPB  512
#define NBLK (NCELLS / MT) // 2048

// smem pitches chosen so bank = (row + col) mod 32 -> conflict free scalar access
#define HP   129           // h tile pitch
#define UP   257           // uv tile pitch
#define OP   65            // out tile pitch (aliases uv region)
#define NH_OFF 4160        // 64*65 floats: nh tile starts after out tile inside uv region
#define NHP  129

#define SMEM_B_FLOATS (MT*HP + MT*UP + 64 + 64)
#define SMEM_B_BYTES  (SMEM_B_FLOATS * 4)

// ---------------- device scratch (static, allocation-free) ----------------
__device__ float g_xc[256];          // xa[128] ++ xg[128]  (x-folded layer-1 bias)
__device__ float g_b2d[64];          // b2a - b2g
__device__ float g_WihP[384 * 64];   // Wih[:, :64] repacked row-aligned (256B rows)
__device__ float g_wt[384];          // Wih[:, 64]  (t-column)
__device__ float g_blk_t[NBLK];      // per-block sum of t
__device__ float g_blk_e[NBLK];      // per-block sum of exp(t)
__device__ float g_blk_wout[NBLK * 64];  // per-block sum of exp(t)*out
__device__ float g_blk_h[NBLK * 128];    // per-block sum of new_h (pre-sync)
__device__ float g_fm[8 * 128];      // faction means
__device__ float g_go[128];          // global opinion (mean of faction means)

// ---------------- Kernel A: tiny precompute ----------------
__global__ __launch_bounds__(512) void kA(
    const float* __restrict__ x,
    const float* __restrict__ W1a, const float* __restrict__ b1a,
    const float* __restrict__ W1g, const float* __restrict__ b1g,
    const float* __restrict__ b2a, const float* __restrict__ b2g,
    const float* __restrict__ Wih)
{
    int tid = threadIdx.x;
    if (tid < 256) {
        const float* W = (tid < 128) ? W1a : W1g;
        const float* b = (tid < 128) ? b1a : b1g;
        int j = tid & 127;
        float s = b[j];
        const float* row = W + j * 192;   // W1[j][0:64] is the x part
        #pragma unroll 8
        for (int k = 0; k < 64; k++) s += row[k] * x[k];
        g_xc[tid] = s;
    }
    if (tid >= 256 && tid < 320) {
        int o = tid - 256;
        g_b2d[o] = b2a[o] - b2g[o];
    }
    for (int i = tid; i < 384 * 64; i += 512) {
        int r = i >> 6, k = i & 63;
        g_WihP[i] = Wih[r * 65 + k];
    }
    if (tid < 384) g_wt[tid] = Wih[tid * 65 + 64];
}

// ---------------- Kernel B: fused per-cell pipeline ----------------
__global__ __launch_bounds__(512) void kB(
    const float* __restrict__ hiddens,
    const float* __restrict__ W1a, const float* __restrict__ W1g,
    const float* __restrict__ W2a, const float* __restrict__ W2g,
    const float* __restrict__ Whh,
    const float* __restrict__ bih, const float* __restrict__ bhh,
    float* __restrict__ dout)
{
    extern __shared__ float sm[];
    float* h_s  = sm;                 // [MT][HP]
    float* uv_s = sm + MT * HP;       // [MT][UP]; later aliased: out [MT][OP], nh at NH_OFF
    float* t_s  = uv_s + MT * UP;     // [64]
    float* e_s  = t_s + 64;           // [64]

    const int tid = threadIdx.x;
    const int blk = blockIdx.x;
    const int w = tid >> 5, l = tid & 31;

    // ---- stage 0: load h tile (coalesced float4 global -> pitched smem) ----
    const float* H = hiddens + (size_t)blk * MT * 128;
    #pragma unroll
    for (int i = tid; i < MT * 32; i += TPB) {       // MT*128/4 float4s
        float4 v = ((const float4*)H)[i];
        int c = i >> 5;
        int k = (i & 31) << 2;
        float* p = h_s + c * HP + k;
        p[0] = v.x; p[1] = v.y; p[2] = v.z; p[3] = v.w;
    }
    __syncthreads();

    // ---- stage 1: uv = relu(h @ W1H^T + xc)   (256 units, K=128) ----
    {
        const float* Wm = (w < 8) ? W1a : W1g;
        const int ub = (w < 8) ? (w << 4) : ((w - 8) << 4);
        float acc0[16], acc1[16];
        #pragma unroll
        for (int j = 0; j < 16; j++) { acc0[j] = 0.f; acc1[j] = 0.f; }
        const float* h0p = h_s + l * HP;
        const float* h1p = h_s + (l + 32) * HP;
        for (int k = 0; k < 128; k += 4) {
            float a0 = h0p[k], a1 = h0p[k+1], a2 = h0p[k+2], a3 = h0p[k+3];
            float b0 = h1p[k], b1 = h1p[k+1], b2 = h1p[k+2], b3 = h1p[k+3];
            #pragma unroll
            for (int j = 0; j < 16; j++) {
                const float4 wv = *(const float4*)(Wm + (ub + j) * 192 + 64 + k);
                acc0[j] += a0 * wv.x + a1 * wv.y + a2 * wv.z + a3 * wv.w;
                acc1[j] += b0 * wv.x + b1 * wv.y + b2 * wv.z + b3 * wv.w;
            }
        }
        const int u0 = w << 4;
        float* uvr0 = uv_s + l * UP;
        float* uvr1 = uv_s + (l + 32) * UP;
        #pragma unroll
        for (int j = 0; j < 16; j++) {
            float b = g_xc[u0 + j];
            uvr0[u0 + j] = fmaxf(acc0[j] + b, 0.f);
            uvr1[u0 + j] = fmaxf(acc1[j] + b, 0.f);
        }
    }
    __syncthreads();

    // ---- stage 2: out = ua@W2a^T - ug@W2g^T + (b2a-b2g) ----
    {
        const int o0 = w << 2;
        float oa0[4], oa1[4];
        #pragma unroll
        for (int j = 0; j < 4; j++) { oa0[j] = 0.f; oa1[j] = 0.f; }
        const float* ua0 = uv_s + l * UP;
        const float* ua1 = uv_s + (l + 32) * UP;
        for (int u = 0; u < 128; u += 4) {
            float p0 = ua0[u],     p1 = ua0[u+1],     p2 = ua0[u+2],     p3 = ua0[u+3];
            float q0 = ua0[128+u], q1 = ua0[128+u+1], q2 = ua0[128+u+2], q3 = ua0[128+u+3];
            float r0 = ua1[u],     r1 = ua1[u+1],     r2 = ua1[u+2],     r3 = ua1[u+3];
            float s0 = ua1[128+u], s1 = ua1[128+u+1], s2 = ua1[128+u+2], s3 = ua1[128+u+3];
            #pragma unroll
            for (int j = 0; j < 4; j++) {
                float4 wa = *(const float4*)(W2a + (o0 + j) * 128 + u);
                float4 wg = *(const float4*)(W2g + (o0 + j) * 128 + u);
                oa0[j] += p0 * wa.x + p1 * wa.y + p2 * wa.z + p3 * wa.w;
                oa0[j] -= q0 * wg.x + q1 * wg.y + q2 * wg.z + q3 * wg.w;
                oa1[j] += r0 * wa.x + r1 * wa.y + r2 * wa.z + r3 * wa.w;
                oa1[j] -= s0 * wg.x + s1 * wg.y + s2 * wg.z + s3 * wg.w;
            }
        }
        __syncthreads();   // all uv reads done; safe to alias region as out tile
        float* ot = uv_s;  // out tile [MT][OP]
        #pragma unroll
        for (int j = 0; j < 4; j++) {
            float b = g_b2d[o0 + j];
            ot[l * OP + o0 + j]        = oa0[j] + b;
            ot[(l + 32) * OP + o0 + j] = oa1[j] + b;
        }
    }
    __syncthreads();

    float* out_t = uv_s;  // [MT][OP]
    // ---- t, e = exp(t) ----
    if (tid < 64) {
        const float* orow = out_t + tid * OP;
        float s = 0.f;
        #pragma unroll
        for (int o = 0; o < 64; o++) { float v = orow[o]; s += v * v; }
        float t = s * (1.f / 64.f);
        t_s[tid] = t;
        e_s[tid] = expf(t);
    }
    __syncthreads();

    // ---- block partials for global reductions (deterministic, no atomics) ----
    if (tid < 64) {
        int o = tid;
        float s = 0.f;
        #pragma unroll 8
        for (int c = 0; c < 64; c++) s += e_s[c] * out_t[c * OP + o];
        g_blk_wout[(size_t)blk * 64 + o] = s;
    } else if (tid == 64) {
        float s = 0.f;
        for (int c = 0; c < 64; c++) s += t_s[c];
        g_blk_t[blk] = s;
    } else if (tid == 96) {
        float s = 0.f;
        for (int c = 0; c < 64; c++) s += e_s[c];
        g_blk_e[blk] = s;
    }

    // ---- stage 3: GRU ----
    float* nh_s = uv_s + NH_OFF;  // [MT][NHP]
    {
        const float* h0p = h_s + l * HP;
        const float* h1p = h_s + (l + 32) * HP;
        const float* o0p = out_t + l * OP;
        const float* o1p = out_t + (l + 32) * OP;
        const float t0 = t_s[l], t1 = t_s[l + 32];

        #pragma unroll 1
        for (int jj = 0; jj < 8; jj++) {
            const int j = (w << 3) + jj;
            const float* whr = Whh + j * 128;
            const float* whz = Whh + (128 + j) * 128;
            const float* whn = Whh + (256 + j) * 128;
            float ar0 = 0.f, az0 = 0.f, an0 = 0.f;
            float ar1 = 0.f, az1 = 0.f, an1 = 0.f;
            for (int k = 0; k < 128; k += 4) {
                float4 wr = *(const float4*)(whr + k);
                float4 wz = *(const float4*)(whz + k);
                float4 wn = *(const float4*)(whn + k);
                float x0 = h0p[k], x1 = h0p[k+1], x2 = h0p[k+2], x3 = h0p[k+3];
                float y0 = h1p[k], y1 = h1p[k+1], y2 = h1p[k+2], y3 = h1p[k+3];
                ar0 += x0*wr.x + x1*wr.y + x2*wr.z + x3*wr.w;
                az0 += x0*wz.x + x1*wz.y + x2*wz.z + x3*wz.w;
                an0 += x0*wn.x + x1*wn.y + x2*wn.z + x3*wn.w;
                ar1 += y0*wr.x + y1*wr.y + y2*wr.z + y3*wr.w;
                az1 += y0*wz.x + y1*wz.y + y2*wz.z + y3*wz.w;
                an1 += y0*wn.x + y1*wn.y + y2*wn.z + y3*wn.w;
            }
            const float* wir = g_WihP + j * 64;
            const float* wiz = g_WihP + (128 + j) * 64;
            const float* win = g_WihP + (256 + j) * 64;
            float br0 = 0.f, bz0 = 0.f, bn0 = 0.f;
            float br1 = 0.f, bz1 = 0.f, bn1 = 0.f;
            for (int k = 0; k < 64; k += 4) {
                float4 wr = *(const float4*)(wir + k);
                float4 wz = *(const float4*)(wiz + k);
                float4 wn = *(const float4*)(win + k);
                float x0 = o0p[k], x1 = o0p[k+1], x2 = o0p[k+2], x3 = o0p[k+3];
                float y0 = o1p[k], y1 = o1p[k+1], y2 = o1p[k+2], y3 = o1p[k+3];
                br0 += x0*wr.x + x1*wr.y + x2*wr.z + x3*wr.w;
                bz0 += x0*wz.x + x1*wz.y + x2*wz.z + x3*wz.w;
                bn0 += x0*wn.x + x1*wn.y + x2*wn.z + x3*wn.w;
                br1 += y0*wr.x + y1*wr.y + y2*wr.z + y3*wr.w;
                bz1 += y0*wz.x + y1*wz.y + y2*wz.z + y3*wz.w;
                bn1 += y0*wn.x + y1*wn.y + y2*wn.z + y3*wn.w;
            }
            float bihr = bih[j], bihz = bih[128 + j], bihn = bih[256 + j];
            float bhr  = bhh[j], bhz  = bhh[128 + j], bhn  = bhh[256 + j];
            float wtr = g_wt[j], wtz = g_wt[128 + j], wtn = g_wt[256 + j];
            {   // cell l
                float gr = (br0 + t0 * wtr + bihr) + (ar0 + bhr);
                float gz = (bz0 + t0 * wtz + bihz) + (az0 + bhz);
                float r = 1.f / (1.f + expf(-gr));
                float z = 1.f / (1.f + expf(-gz));
                float n = tanhf(bn0 + t0 * wtn + bihn + r * (an0 + bhn));
                float h = h0p[j];
                nh_s[l * NHP + j] = (1.f - z) * n + z * h;
            }
            {   // cell l+32
                float gr = (br1 + t1 * wtr + bihr) + (ar1 + bhr);
                float gz = (bz1 + t1 * wtz + bihz) + (az1 + bhz);
                float r = 1.f / (1.f + expf(-gr));
                float z = 1.f / (1.f + expf(-gz));
                float n = tanhf(bn1 + t1 * wtn + bihn + r * (an1 + bhn));
                float h = h1p[j];
                nh_s[(l + 32) * NHP + j] = (1.f - z) * n + z * h;
            }
        }
    }
    __syncthreads();

    // ---- store new_h (pre-sync) into d_out, coalesced ----
    float* NH = dout + 65 + (size_t)blk * MT * 128;
    #pragma unroll
    for (int i = tid; i < MT * 128; i += TPB) {
        int c = i >> 7, k = i & 127;
        NH[i] = nh_s[c * NHP + k];
    }
    // ---- per-block new_h sum (for faction means) ----
    if (tid < 128) {
        float s = 0.f;
        #pragma unroll 8
        for (int c = 0; c < 64; c++) s += nh_s[c * NHP + tid];
        g_blk_h[(size_t)blk * 128 + tid] = s;
    }
}

// ---------------- Kernel C: global reductions + head ----------------
__global__ __launch_bounds__(1024) void kC(
    const float* __restrict__ Wo, const float* __restrict__ bo,
    float* __restrict__ dout)
{
    __shared__ float s_red[1024];
    __shared__ float s_red2[1024];
    __shared__ float s_comb[64];
    __shared__ float s_esum;
    const int tid = threadIdx.x;

    // faction sums: thread = (faction f, hidden j)
    {
        int f = tid >> 7, j = tid & 127;
        const float* p = g_blk_h + (size_t)(f * 256) * 128 + j;
        float s = 0.f;
        #pragma unroll 8
        for (int b = 0; b < 256; b++) s += p[b * 128];
        g_fm[f * 128 + j] = s * (1.f / 16384.f);
        s_red[tid] = s;
    }
    __syncthreads();
    if (tid < 128) {
        float g = 0.f;
        #pragma unroll
        for (int f = 0; f < 8; f++) g += s_red[f * 128 + tid];
        g_go[tid] = g * (1.f / (float)NCELLS);
    }
    __syncthreads();

    // weighted-out numerator: 16 chunks x 64 outputs
    {
        int o = tid & 63, ch = tid >> 6;
        const float* p = g_blk_wout + (size_t)(ch * 128) * 64 + o;
        float s = 0.f;
        #pragma unroll 8
        for (int b = 0; b < 128; b++) s += p[b * 64];
        s_red[tid] = s;
    }
    __syncthreads();
    if (tid < 64) {
        float s = 0.f;
        #pragma unroll
        for (int ch = 0; ch < 16; ch++) s += s_red[ch * 64 + tid];
        s_comb[tid] = s;
    }
    __syncthreads();

    // exp-sum and t-sum, one shared tree for both
    float se = 0.f, st = 0.f;
    for (int i = tid; i < NBLK; i += 1024) { se += g_blk_e[i]; st += g_blk_t[i]; }
    s_red[tid] = se;
    s_red2[tid] = st;
    __syncthreads();
    for (int off = 512; off > 0; off >>= 1) {
        if (tid < off) { s_red[tid] += s_red[tid + off]; s_red2[tid] += s_red2[tid + off]; }
        __syncthreads();
    }
    if (tid == 0) {
        s_esum = s_red[0];
        dout[64] = s_red2[0] * (1.f / (float)NCELLS);
    }
    __syncthreads();

    // combined = wout / esum ; pred = combined @ Wo^T + bo
    if (tid < 64) s_comb[tid] *= (1.f / s_esum);
    __syncthreads();
    if (tid < 64) {
        float p = bo[tid];
        const float* wr = Wo + tid * 64;
        #pragma unroll 8
        for (int o = 0; o < 64; o++) p += wr[o] * s_comb[o];
        dout[tid] = p;
    }
}

// ---------------- Kernel D: faction sync (in-place on d_out new_h) ----------------
// new_h starts at dout+65 (260-byte offset): not 16B aligned, so scalar 32-bit
// accesses (fully coalesced) are used. The pass is HBM-bound; access width is
// not the binding constraint at this footprint (128 MB RMW).
__global__ __launch_bounds__(512) void kD(float* __restrict__ nh, const void* __restrict__ stepPtr)
{
    // robust step decode: handles int32 / int64(LE) / float32 scalar
    int iv = *(const int*)stepPtr;
    int step = (iv >= 0 && iv < 1000000) ? iv : (int)(*(const float*)stepPtr);
    const bool debate = (step > 5);

    unsigned base = blockIdx.x * 512u + threadIdx.x;
    const unsigned stride = 2048u * 512u;
    #pragma unroll 4
    for (int r = 0; r < 16; r++) {
        unsigned e = base + (unsigned)r * stride;   // element index < 2^24, exact coverage
        unsigned cell = e >> 7;
        unsigned j = e & 127u;
        unsigned f = cell >> 14;           // 16384 cells per faction
        unsigned pos = cell & 16383u;
        float v = nh[e];
        v = 0.85f * v + 0.15f * g_fm[f * 128 + j];
        if (debate && pos < 4096u) v = 0.85f * v + 0.15f * g_go[j];
        nh[e] = v;
    }
}

// ---------------- launcher ----------------
extern "C" void kernel_launch(void* const* d_in, const int* in_sizes, int n_in,
                              void* d_out, int out_size)
{
    const float* x    = (const float*)d_in[0];
    const float* hid  = (const float*)d_in[1];
    const float* W1a  = (const float*)d_in[2];
    const float* b1a  = (const float*)d_in[3];
    const float* W2a  = (const float*)d_in[4];
    const float* b2a  = (const float*)d_in[5];
    const float* W1g  = (const float*)d_in[6];
    const float* b1g  = (const float*)d_in[7];
    const float* W2g  = (const float*)d_in[8];
    const float* b2g  = (const float*)d_in[9];
    const float* Wih  = (const float*)d_in[10];
    const float* Whh  = (const float*)d_in[11];
    const float* bih  = (const float*)d_in[12];
    const float* bhh  = (const float*)d_in[13];
    const float* Wo   = (const float*)d_in[14];
    const float* bo   = (const float*)d_in[15];
    const void*  step = (n_in > 16) ? (const void*)d_in[16] : (const void*)d_in[15];

    float* out = (float*)d_out;
    float* nh  = out + 65;

    cudaFuncSetAttribute(kB, cudaFuncAttributeMaxDynamicSharedMemorySize, SMEM_B_BYTES);

    kA<<<1, 512>>>(x, W1a, b1a, W1g, b1g, b2a, b2g, Wih);
    kB<<<NBLK, TPB, SMEM_B_BYTES>>>(hid, W1a, W1g, W2a, W2g, Whh, bih, bhh, out);
    kC<<<1, 1024>>>(Wo, bo, out);
    kD<<<2048, 512>>>(nh, step);
}

// round 7
// speedup vs baseline: 4.5505x; 4.5505x over previous
#include <cuda_runtime.h>
#include <stdint.h>
#include <math.h>

// ---------------- problem constants ----------------
#define NCELLS 131072
#define MT   64
#define TPB  512
#define NBLK (NCELLS / MT)   // 2048

// ---------------- smem layout (floats), pitches chosen so bank = (4*gid+tig) distinct
#define HP2   132            // h tile pitch      (132 % 32 == 4)
#define C1P   260            // C1 tile pitch     (260 % 32 == 4)
#define OUTP  68             // out tile pitch    (68  % 32 == 4)
#define OFF_H    0
#define OFF_C1   (64*HP2)                 // 8448
#define OFF_OUT  (OFF_C1 + 64*C1P)        // 25088
#define OFF_T    (OFF_OUT + 64*OUTP)      // 29440
#define OFF_E    (OFF_T + 64)             // 29504
#define OFF_XC   (OFF_E + 64)             // 29568
#define OFF_B2D  (OFF_XC + 256)           // 29824
#define OFF_BRZ  (OFF_B2D + 64)           // 29888
#define OFF_BNI  (OFF_BRZ + 256)          // 30144
#define OFF_BNH  (OFF_BNI + 128)          // 30272
#define OFF_WT   (OFF_BNH + 128)          // 30400
#define SMEM_KB_FLOATS (OFF_WT + 384)     // 30784
#define SMEM_KB_BYTES  (SMEM_KB_FLOATS * 4)

// ---------------- device scratch (static, allocation-free) ----------------
// fragment-packed tf32 weights: [ktPair][ntile][lane] -> {b0_k0,b1_k0,b0_k1,b1_k1}
__device__ uint4 g_B1[8 * 32 * 32];     // stage1  K=128,N=256   131 KB
__device__ uint4 g_B2[16 * 8 * 32];     // stage2  K=256,N=64    65.5 KB (sign-folded)
__device__ uint4 g_B3[8 * 48 * 32];     // GRU Whh K=128,N=384   196 KB
__device__ uint4 g_B4[4 * 48 * 32];     // GRU Wih K=64, N=384   98 KB
__device__ float g_xc[256];             // x-folded layer1 bias (exact fp32)
__device__ float g_b2d[64];             // b2a - b2g
__device__ float g_brz[256];            // bih+bhh for r,z rows
__device__ float g_bni[128];            // bih n rows
__device__ float g_bnh[128];            // bhh n rows
__device__ float g_wt[384];             // Wih[:,64]
__device__ float g_blk_t[NBLK];
__device__ float g_blk_e[NBLK];
__device__ float g_blk_wout[NBLK * 64];
__device__ float g_blk_h[NBLK * 128];
__device__ float g_fm[8 * 128];
__device__ float g_go[128];

// ---------------- helpers ----------------
__device__ __forceinline__ unsigned f2tf(float f) {
    unsigned u;
    asm("cvt.rna.tf32.f32 %0, %1;" : "=r"(u) : "f"(f));
    return u;
}
__device__ __forceinline__ void mma8(float* c,
    unsigned a0, unsigned a1, unsigned a2, unsigned a3,
    unsigned b0, unsigned b1)
{
    asm volatile(
        "mma.sync.aligned.m16n8k8.row.col.f32.tf32.tf32.f32 "
        "{%0,%1,%2,%3},{%4,%5,%6,%7},{%8,%9},{%0,%1,%2,%3};"
        : "+f"(c[0]), "+f"(c[1]), "+f"(c[2]), "+f"(c[3])
        : "r"(a0), "r"(a1), "r"(a2), "r"(a3), "r"(b0), "r"(b1));
}
__device__ __forceinline__ float sigmoid_f(float x) {
    return 1.f / (1.f + __expf(-x));
}

// ---------------- Kernel A: pack weights into fragment order (tf32) ----------------
// flat tasks: [0,8192) B1 | [8192,12288) B2 | [12288,24576) B3 | [24576,30720) B4
//             [30720,30976) xc | [30976,31040) b2d | [31040,31424) wt
//             [31424,31680) brz | [31680,31808) bni | [31808,31936) bnh
__global__ __launch_bounds__(512) void kA(
    const float* __restrict__ x,
    const float* __restrict__ W1a, const float* __restrict__ b1a,
    const float* __restrict__ W1g, const float* __restrict__ b1g,
    const float* __restrict__ b2a, const float* __restrict__ b2g,
    const float* __restrict__ W2a, const float* __restrict__ W2g,
    const float* __restrict__ Wih, const float* __restrict__ Whh,
    const float* __restrict__ bih, const float* __restrict__ bhh)
{
    int id = blockIdx.x * 512 + threadIdx.x;
    if (id < 8192) {                                  // B1: B[k][u]=W1[u][64+k]
        int p = id >> 10, rem = id & 1023;
        int nt = rem >> 5, lane = rem & 31;
        int tig = lane & 3, gid = lane >> 2;
        int u = nt * 8 + gid;
        const float* wr = ((u < 128) ? (W1a + u * 192) : (W1g + (u - 128) * 192)) + 64 + 16 * p + tig;
        g_B1[id] = make_uint4(f2tf(wr[0]), f2tf(wr[4]), f2tf(wr[8]), f2tf(wr[12]));
    } else if (id < 12288) {                          // B2: +W2a / -W2g
        int i = id - 8192;
        int p = i >> 8, rem = i & 255;
        int nt = rem >> 5, lane = rem & 31;
        int tig = lane & 3, gid = lane >> 2;
        int o = nt * 8 + gid;
        if (p < 8) {
            const float* wr = W2a + o * 128 + 16 * p + tig;
            g_B2[i] = make_uint4(f2tf(wr[0]), f2tf(wr[4]), f2tf(wr[8]), f2tf(wr[12]));
        } else {
            const float* wr = W2g + o * 128 + 16 * (p - 8) + tig;
            g_B2[i] = make_uint4(f2tf(-wr[0]), f2tf(-wr[4]), f2tf(-wr[8]), f2tf(-wr[12]));
        }
    } else if (id < 24576) {                          // B3: Whh[j][k]
        int i = id - 12288;
        int p = i / 1536, rem = i % 1536;
        int nt = rem >> 5, lane = rem & 31;
        int tig = lane & 3, gid = lane >> 2;
        int j = nt * 8 + gid;
        const float* wr = Whh + j * 128 + 16 * p + tig;
        g_B3[i] = make_uint4(f2tf(wr[0]), f2tf(wr[4]), f2tf(wr[8]), f2tf(wr[12]));
    } else if (id < 30720) {                          // B4: Wih[j][k], k<64
        int i = id - 24576;
        int p = i / 1536, rem = i % 1536;
        int nt = rem >> 5, lane = rem & 31;
        int tig = lane & 3, gid = lane >> 2;
        int j = nt * 8 + gid;
        const float* wr = Wih + j * 65 + 16 * p + tig;
        g_B4[i] = make_uint4(f2tf(wr[0]), f2tf(wr[4]), f2tf(wr[8]), f2tf(wr[12]));
    } else if (id < 30976) {                          // xc (exact fp32 x-fold)
        int u = id - 30720;
        const float* W = (u < 128) ? W1a : W1g;
        const float* b = (u < 128) ? b1a : b1g;
        int j = u & 127;
        float s = b[j];
        const float* row = W + j * 192;
        #pragma unroll 8
        for (int k = 0; k < 64; k++) s += row[k] * x[k];
        g_xc[u] = s;
    } else if (id < 31040) {
        int o = id - 30976;
        g_b2d[o] = b2a[o] - b2g[o];
    } else if (id < 31424) {
        int j = id - 31040;
        g_wt[j] = Wih[j * 65 + 64];
    } else if (id < 31680) {
        int j = id - 31424;
        g_brz[j] = bih[j] + bhh[j];
    } else if (id < 31808) {
        int j = id - 31680;
        g_bni[j] = bih[256 + j];
    } else if (id < 31936) {
        int j = id - 31808;
        g_bnh[j] = bhh[256 + j];
    }
}

// ---------------- Kernel B: fused per-cell pipeline (tf32 tensor cores) ----------------
__global__ __launch_bounds__(512, 1) void kB(
    const float* __restrict__ hiddens,
    float* __restrict__ dout)
{
    extern __shared__ float sm[];
    float* h_s   = sm + OFF_H;
    float* C1    = sm + OFF_C1;
    float* out_s = sm + OFF_OUT;
    float* t_s   = sm + OFF_T;
    float* e_s   = sm + OFF_E;
    float* xc_s  = sm + OFF_XC;
    float* b2d_s = sm + OFF_B2D;
    float* brz_s = sm + OFF_BRZ;
    float* bni_s = sm + OFF_BNI;
    float* bnh_s = sm + OFF_BNH;
    float* wt_s  = sm + OFF_WT;

    const int tid  = threadIdx.x;
    const int blk  = blockIdx.x;
    const int w    = tid >> 5;
    const int lane = tid & 31;
    const int tig  = lane & 3;
    const int gid  = lane >> 2;

    // ---- stage 0: load h tile + constant tables ----
    const float* H = hiddens + (size_t)blk * MT * 128;
    #pragma unroll
    for (int i = tid; i < MT * 32; i += TPB) {
        float4 v = ((const float4*)H)[i];
        int c = i >> 5, k = (i & 31) << 2;
        float* p = h_s + c * HP2 + k;
        p[0] = v.x; p[1] = v.y; p[2] = v.z; p[3] = v.w;
    }
    if (tid < 256) { xc_s[tid] = g_xc[tid]; brz_s[tid] = g_brz[tid]; }
    if (tid < 64)  { b2d_s[tid] = g_b2d[tid]; }
    if (tid < 128) { bni_s[tid] = g_bni[tid]; bnh_s[tid] = g_bnh[tid]; }
    if (tid < 384) { wt_s[tid] = g_wt[tid]; }
    __syncthreads();

    // ---- stage 1: C1[64x256] = relu(h @ B1 + xc) ----
    {
        const int mt = w & 3, ng = w >> 2;       // nt = ng*8 + ni
        const int r0 = mt * 16 + gid, r1 = r0 + 8;
        float acc[8][4];
        #pragma unroll
        for (int i = 0; i < 8; i++)
            #pragma unroll
            for (int j = 0; j < 4; j++) acc[i][j] = 0.f;
        #pragma unroll
        for (int p = 0; p < 8; p++) {
            const float* hp0 = h_s + r0 * HP2 + 16 * p + tig;
            const float* hp1 = h_s + r1 * HP2 + 16 * p + tig;
            unsigned a00 = f2tf(hp0[0]),  a01 = f2tf(hp1[0]),  a02 = f2tf(hp0[4]),  a03 = f2tf(hp1[4]);
            unsigned a10 = f2tf(hp0[8]),  a11 = f2tf(hp1[8]),  a12 = f2tf(hp0[12]), a13 = f2tf(hp1[12]);
            const uint4* bp = g_B1 + ((p * 32 + ng * 8) * 32 + lane);
            #pragma unroll
            for (int ni = 0; ni < 8; ni++) {
                uint4 bv = bp[ni * 32];
                mma8(acc[ni], a00, a01, a02, a03, bv.x, bv.y);
                mma8(acc[ni], a10, a11, a12, a13, bv.z, bv.w);
            }
        }
        #pragma unroll
        for (int ni = 0; ni < 8; ni++) {
            int cb = (ng * 8 + ni) * 8 + 2 * tig;
            float x0 = xc_s[cb], x1 = xc_s[cb + 1];
            C1[r0 * C1P + cb]     = fmaxf(acc[ni][0] + x0, 0.f);
            C1[r0 * C1P + cb + 1] = fmaxf(acc[ni][1] + x1, 0.f);
            C1[r1 * C1P + cb]     = fmaxf(acc[ni][2] + x0, 0.f);
            C1[r1 * C1P + cb + 1] = fmaxf(acc[ni][3] + x1, 0.f);
        }
    }
    __syncthreads();

    // ---- stage 2: out[64x64] = C1 @ B2 + b2d  (a - g fused via sign-folded B2) ----
    {
        const int mt = w & 3, np = w >> 2;       // nt = np*2 + {0,1}
        const int r0 = mt * 16 + gid, r1 = r0 + 8;
        float acc[2][4];
        #pragma unroll
        for (int i = 0; i < 2; i++)
            #pragma unroll
            for (int j = 0; j < 4; j++) acc[i][j] = 0.f;
        #pragma unroll
        for (int p = 0; p < 16; p++) {
            const float* cp0 = C1 + r0 * C1P + 16 * p + tig;
            const float* cp1 = C1 + r1 * C1P + 16 * p + tig;
            unsigned a00 = f2tf(cp0[0]),  a01 = f2tf(cp1[0]),  a02 = f2tf(cp0[4]),  a03 = f2tf(cp1[4]);
            unsigned a10 = f2tf(cp0[8]),  a11 = f2tf(cp1[8]),  a12 = f2tf(cp0[12]), a13 = f2tf(cp1[12]);
            const uint4* bp = g_B2 + ((p * 8 + np * 2) * 32 + lane);
            #pragma unroll
            for (int ni = 0; ni < 2; ni++) {
                uint4 bv = bp[ni * 32];
                mma8(acc[ni], a00, a01, a02, a03, bv.x, bv.y);
                mma8(acc[ni], a10, a11, a12, a13, bv.z, bv.w);
            }
        }
        #pragma unroll
        for (int ni = 0; ni < 2; ni++) {
            int cb = (np * 2 + ni) * 8 + 2 * tig;
            float x0 = b2d_s[cb], x1 = b2d_s[cb + 1];
            out_s[r0 * OUTP + cb]     = acc[ni][0] + x0;
            out_s[r0 * OUTP + cb + 1] = acc[ni][1] + x1;
            out_s[r1 * OUTP + cb]     = acc[ni][2] + x0;
            out_s[r1 * OUTP + cb + 1] = acc[ni][3] + x1;
        }
    }
    __syncthreads();

    // ---- t, e (warps 0-1, overlapped with GRU mma of all warps) ----
    if (tid < 64) {
        const float* orow = out_s + tid * OUTP;
        float s = 0.f;
        #pragma unroll
        for (int o = 0; o < 64; o++) { float v = orow[o]; s += v * v; }
        float t = s * (1.f / 64.f);
        t_s[tid] = t;
        e_s[tid] = expf(t);
    }

    // ---- GRU: gates via tensor cores, elementwise in registers ----
    {
        const int mt = w & 3, jq = w >> 2;      // j-range [jq*32, jq*32+32)
        const int r0 = mt * 16 + gid, r1 = r0 + 8;
        float aR[4][4], aZ[4][4], aNh[4][4], aNi[4][4];
        #pragma unroll
        for (int i = 0; i < 4; i++)
            #pragma unroll
            for (int j = 0; j < 4; j++) { aR[i][j] = 0.f; aZ[i][j] = 0.f; aNh[i][j] = 0.f; aNi[i][j] = 0.f; }

        // h-side: gh = h @ Whh^T  (K=128)
        #pragma unroll
        for (int p = 0; p < 8; p++) {
            const float* hp0 = h_s + r0 * HP2 + 16 * p + tig;
            const float* hp1 = h_s + r1 * HP2 + 16 * p + tig;
            unsigned a00 = f2tf(hp0[0]),  a01 = f2tf(hp1[0]),  a02 = f2tf(hp0[4]),  a03 = f2tf(hp1[4]);
            unsigned a10 = f2tf(hp0[8]),  a11 = f2tf(hp1[8]),  a12 = f2tf(hp0[12]), a13 = f2tf(hp1[12]);
            #pragma unroll
            for (int jn = 0; jn < 4; jn++) {
                int tb = p * 48 + jq * 4 + jn;
                uint4 bR = g_B3[(tb)      * 32 + lane];
                uint4 bZ = g_B3[(tb + 16) * 32 + lane];
                uint4 bN = g_B3[(tb + 32) * 32 + lane];
                mma8(aR[jn],  a00, a01, a02, a03, bR.x, bR.y);
                mma8(aR[jn],  a10, a11, a12, a13, bR.z, bR.w);
                mma8(aZ[jn],  a00, a01, a02, a03, bZ.x, bZ.y);
                mma8(aZ[jn],  a10, a11, a12, a13, bZ.z, bZ.w);
                mma8(aNh[jn], a00, a01, a02, a03, bN.x, bN.y);
                mma8(aNh[jn], a10, a11, a12, a13, bN.z, bN.w);
            }
        }
        // i-side: gi = out @ Wih^T (K=64); r,z sum into same accs, n kept separate
        #pragma unroll
        for (int p = 0; p < 4; p++) {
            const float* op0 = out_s + r0 * OUTP + 16 * p + tig;
            const float* op1 = out_s + r1 * OUTP + 16 * p + tig;
            unsigned a00 = f2tf(op0[0]),  a01 = f2tf(op1[0]),  a02 = f2tf(op0[4]),  a03 = f2tf(op1[4]);
            unsigned a10 = f2tf(op0[8]),  a11 = f2tf(op1[8]),  a12 = f2tf(op0[12]), a13 = f2tf(op1[12]);
            #pragma unroll
            for (int jn = 0; jn < 4; jn++) {
                int tb = p * 48 + jq * 4 + jn;
                uint4 bR = g_B4[(tb)      * 32 + lane];
                uint4 bZ = g_B4[(tb + 16) * 32 + lane];
                uint4 bN = g_B4[(tb + 32) * 32 + lane];
                mma8(aR[jn],  a00, a01, a02, a03, bR.x, bR.y);
                mma8(aR[jn],  a10, a11, a12, a13, bR.z, bR.w);
                mma8(aZ[jn],  a00, a01, a02, a03, bZ.x, bZ.y);
                mma8(aZ[jn],  a10, a11, a12, a13, bZ.z, bZ.w);
                mma8(aNi[jn], a00, a01, a02, a03, bN.x, bN.y);
                mma8(aNi[jn], a10, a11, a12, a13, bN.z, bN.w);
            }
        }
        // all h_s / out_s reads done; t_s ready after this barrier
        __syncthreads();

        const float t0 = t_s[r0], t1 = t_s[r1];
        #pragma unroll
        for (int jn = 0; jn < 4; jn++) {
            int j0 = (jq * 4 + jn) * 8 + 2 * tig;
            #pragma unroll
            for (int cc = 0; cc < 2; cc++) {
                int j = j0 + cc;
                float brzr = brz_s[j],        wtr = wt_s[j];
                float brzz = brz_s[128 + j],  wtz = wt_s[128 + j];
                float bni  = bni_s[j],        bnh = bnh_s[j], wtn = wt_s[256 + j];
                {   // row r0 -> acc index cc
                    float r = sigmoid_f(aR[jn][cc] + brzr + t0 * wtr);
                    float z = sigmoid_f(aZ[jn][cc] + brzz + t0 * wtz);
                    float n = tanhf(aNi[jn][cc] + t0 * wtn + bni + r * (aNh[jn][cc] + bnh));
                    float hv = h_s[r0 * HP2 + j];
                    h_s[r0 * HP2 + j] = (1.f - z) * n + z * hv;
                }
                {   // row r1 -> acc index 2+cc
                    float r = sigmoid_f(aR[jn][2 + cc] + brzr + t1 * wtr);
                    float z = sigmoid_f(aZ[jn][2 + cc] + brzz + t1 * wtz);
                    float n = tanhf(aNi[jn][2 + cc] + t1 * wtn + bni + r * (aNh[jn][2 + cc] + bnh));
                    float hv = h_s[r1 * HP2 + j];
                    h_s[r1 * HP2 + j] = (1.f - z) * n + z * hv;
                }
            }
        }
    }
    __syncthreads();

    // ---- store new_h (pre-sync) coalesced; block partials ----
    float* NH = dout + 65 + (size_t)blk * MT * 128;
    #pragma unroll
    for (int i = tid; i < MT * 128; i += TPB) {
        int c = i >> 7, k = i & 127;
        NH[i] = h_s[c * HP2 + k];
    }
    if (tid < 128) {
        float s = 0.f;
        #pragma unroll 8
        for (int c = 0; c < 64; c++) s += h_s[c * HP2 + tid];
        g_blk_h[(size_t)blk * 128 + tid] = s;
    }
    if (tid < 64) {
        float s = 0.f;
        #pragma unroll 8
        for (int c = 0; c < 64; c++) s += e_s[c] * out_s[c * OUTP + tid];
        g_blk_wout[(size_t)blk * 64 + tid] = s;
    } else if (tid == 64) {
        float s = 0.f;
        for (int c = 0; c < 64; c++) s += t_s[c];
        g_blk_t[blk] = s;
    } else if (tid == 96) {
        float s = 0.f;
        for (int c = 0; c < 64; c++) s += e_s[c];
        g_blk_e[blk] = s;
    }
}

// ---------------- Kernel C: global reductions + head ----------------
__global__ __launch_bounds__(1024) void kC(
    const float* __restrict__ Wo, const float* __restrict__ bo,
    float* __restrict__ dout)
{
    __shared__ float s_red[1024];
    __shared__ float s_red2[1024];
    __shared__ float s_comb[64];
    __shared__ float s_esum;
    const int tid = threadIdx.x;

    {
        int f = tid >> 7, j = tid & 127;
        const float* p = g_blk_h + (size_t)(f * 256) * 128 + j;
        float s = 0.f;
        #pragma unroll 8
        for (int b = 0; b < 256; b++) s += p[b * 128];
        g_fm[f * 128 + j] = s * (1.f / 16384.f);
        s_red[tid] = s;
    }
    __syncthreads();
    if (tid < 128) {
        float g = 0.f;
        #pragma unroll
        for (int f = 0; f < 8; f++) g += s_red[f * 128 + tid];
        g_go[tid] = g * (1.f / (float)NCELLS);
    }
    __syncthreads();

    {
        int o = tid & 63, ch = tid >> 6;
        const float* p = g_blk_wout + (size_t)(ch * 128) * 64 + o;
        float s = 0.f;
        #pragma unroll 8
        for (int b = 0; b < 128; b++) s += p[b * 64];
        s_red[tid] = s;
    }
    __syncthreads();
    if (tid < 64) {
        float s = 0.f;
        #pragma unroll
        for (int ch = 0; ch < 16; ch++) s += s_red[ch * 64 + tid];
        s_comb[tid] = s;
    }
    __syncthreads();

    float se = 0.f, st = 0.f;
    for (int i = tid; i < NBLK; i += 1024) { se += g_blk_e[i]; st += g_blk_t[i]; }
    s_red[tid] = se;
    s_red2[tid] = st;
    __syncthreads();
    for (int off = 512; off > 0; off >>= 1) {
        if (tid < off) { s_red[tid] += s_red[tid + off]; s_red2[tid] += s_red2[tid + off]; }
        __syncthreads();
    }
    if (tid == 0) {
        s_esum = s_red[0];
        dout[64] = s_red2[0] * (1.f / (float)NCELLS);
    }
    __syncthreads();

    if (tid < 64) s_comb[tid] *= (1.f / s_esum);
    __syncthreads();
    if (tid < 64) {
        float p = bo[tid];
        const float* wr = Wo + tid * 64;
        #pragma unroll 8
        for (int o = 0; o < 64; o++) p += wr[o] * s_comb[o];
        dout[tid] = p;
    }
}

// ---------------- Kernel D: faction sync (in-place on d_out new_h) ----------------
__global__ __launch_bounds__(512) void kD(float* __restrict__ nh, const void* __restrict__ stepPtr)
{
    int iv = *(const int*)stepPtr;
    int step = (iv >= 0 && iv < 1000000) ? iv : (int)(*(const float*)stepPtr);
    const bool debate = (step > 5);

    unsigned base = blockIdx.x * 512u + threadIdx.x;
    const unsigned stride = 2048u * 512u;
    #pragma unroll 4
    for (int r = 0; r < 16; r++) {
        unsigned e = base + (unsigned)r * stride;
        unsigned cell = e >> 7;
        unsigned j = e & 127u;
        unsigned f = cell >> 14;
        unsigned pos = cell & 16383u;
        float v = nh[e];
        v = 0.85f * v + 0.15f * g_fm[f * 128 + j];
        if (debate && pos < 4096u) v = 0.85f * v + 0.15f * g_go[j];
        nh[e] = v;
    }
}

// ---------------- launcher ----------------
extern "C" void kernel_launch(void* const* d_in, const int* in_sizes, int n_in,
                              void* d_out, int out_size)
{
    const float* x    = (const float*)d_in[0];
    const float* hid  = (const float*)d_in[1];
    const float* W1a  = (const float*)d_in[2];
    const float* b1a  = (const float*)d_in[3];
    const float* W2a  = (const float*)d_in[4];
    const float* b2a  = (const float*)d_in[5];
    const float* W1g  = (const float*)d_in[6];
    const float* b1g  = (const float*)d_in[7];
    const float* W2g  = (const float*)d_in[8];
    const float* b2g  = (const float*)d_in[9];
    const float* Wih  = (const float*)d_in[10];
    const float* Whh  = (const float*)d_in[11];
    const float* bih  = (const float*)d_in[12];
    const float* bhh  = (const float*)d_in[13];
    const float* Wo   = (const float*)d_in[14];
    const float* bo   = (const float*)d_in[15];
    const void*  step = (n_in > 16) ? (const void*)d_in[16] : (const void*)d_in[15];

    float* out = (float*)d_out;
    float* nh  = out + 65;

    cudaFuncSetAttribute(kB, cudaFuncAttributeMaxDynamicSharedMemorySize, SMEM_KB_BYTES);

    kA<<<63, 512>>>(x, W1a, b1a, W1g, b1g, b2a, b2g, W2a, W2g, Wih, Whh, bih, bhh);
    kB<<<NBLK, TPB, SMEM_KB_BYTES>>>(hid, out);
    kC<<<1, 1024>>>(Wo, bo, out);
    kD<<<2048, 512>>>(nh, step);
}

// round 8
// speedup vs baseline: 6.2803x; 1.3801x over previous
#include <cuda_runtime.h>
#include <cuda_fp16.h>
#include <stdint.h>
#include <math.h>

// ---------------- problem constants ----------------
#define NCELLS 131072
#define MT   64
#define TPB  512
#define NBLK (NCELLS / MT)   // 2048

// ---------------- smem layout ----------------
// pitches: fp32 pitch 132 words (132%32==4), half pitches 136/264/72 halves (68/132/36 words)
#define HP    132            // h_s fp32 pitch (floats)
#define HHP   136            // h_h half pitch (halves)
#define C1HP  264            // C1h half pitch (halves)
#define OHP   72             // out_h half pitch (halves)
#define PP    68             // P0/P1 fp32 pitch

#define OFF_H    0                        // 64*132      = 8448 floats
#define OFF_HH   8448                     // 64*136 h    = 4352 floats
#define OFF_C1H  12800                    // 64*264 h    = 8448 floats
#define OFF_OUTH 21248                    // 64*72 h     = 2304 floats
#define OFF_P0   23552                    // 64*68       = 4352
#define OFF_P1   27904                    // 4352
#define OFF_T    32256
#define OFF_E    32320
#define OFF_XC   32384                    // 256
#define OFF_B2D  32640                    // 64
#define OFF_BRZ  32704                    // 256
#define OFF_BNI  32960                    // 128
#define OFF_BNH  33088                    // 128
#define OFF_WT   33216                    // 384
#define SMEM_KB_FLOATS 33600
#define SMEM_KB_BYTES  (SMEM_KB_FLOATS * 4)

// ---------------- device scratch (static, allocation-free) ----------------
// half2-fragment-packed weights for mma.m16n8k16: entry = uint2 {b0(k0..7), b1(k8..15)}
__device__ uint2 g_B1h[8 * 32 * 32];     // stage1  K=128,N=256    65 KB
__device__ uint2 g_B2h[16 * 8 * 32];     // stage2  K=256,N=64     32 KB (sign-folded)
__device__ uint2 g_B3h[8 * 48 * 32];     // GRU Whh K=128,N=384    98 KB
__device__ uint2 g_B4h[4 * 48 * 32];     // GRU Wih K=64, N=384    49 KB
__device__ float g_xc[256];              // x-folded layer1 bias (exact fp32)
__device__ float g_b2d[64];              // b2a - b2g
__device__ float g_brz[256];             // bih+bhh for r,z rows
__device__ float g_bni[128];             // bih n rows
__device__ float g_bnh[128];             // bhh n rows
__device__ float g_wt[384];              // Wih[:,64]
__device__ float g_blk_t[NBLK];
__device__ float g_blk_e[NBLK];
__device__ float g_blk_wout[NBLK * 64];
__device__ float g_blk_h[NBLK * 128];
__device__ float g_fm[8 * 128];
__device__ float g_go[128];

// ---------------- helpers ----------------
__device__ __forceinline__ unsigned packh2(float lo, float hi) {
    __half2 h = __floats2half2_rn(lo, hi);
    return *(unsigned*)&h;
}
__device__ __forceinline__ void mma16(float* c,
    unsigned a0, unsigned a1, unsigned a2, unsigned a3,
    unsigned b0, unsigned b1)
{
    asm volatile(
        "mma.sync.aligned.m16n8k16.row.col.f32.f16.f16.f32 "
        "{%0,%1,%2,%3},{%4,%5,%6,%7},{%8,%9},{%0,%1,%2,%3};"
        : "+f"(c[0]), "+f"(c[1]), "+f"(c[2]), "+f"(c[3])
        : "r"(a0), "r"(a1), "r"(a2), "r"(a3), "r"(b0), "r"(b1));
}
__device__ __forceinline__ float sigmoid_f(float x) {
    return 1.f / (1.f + __expf(-x));
}

// ---------------- Kernel A: pack weights into fp16 fragment order ----------------
// flat tasks: [0,8192) B1h | [8192,12288) B2h | [12288,24576) B3h | [24576,30720) B4h
//             [30720,30976) xc | [30976,31040) b2d | [31040,31424) wt
//             [31424,31680) brz | [31680,31808) bni | [31808,31936) bnh
__global__ __launch_bounds__(512) void kA(
    const float* __restrict__ x,
    const float* __restrict__ W1a, const float* __restrict__ b1a,
    const float* __restrict__ W1g, const float* __restrict__ b1g,
    const float* __restrict__ b2a, const float* __restrict__ b2g,
    const float* __restrict__ W2a, const float* __restrict__ W2g,
    const float* __restrict__ Wih, const float* __restrict__ Whh,
    const float* __restrict__ bih, const float* __restrict__ bhh)
{
    int id = blockIdx.x * 512 + threadIdx.x;
    if (id < 8192) {                                  // B1h: B[k][u]=W1[u][64+k]
        int grp = id >> 10, rem = id & 1023;
        int nt = rem >> 5, lane = rem & 31;
        int t = lane & 3, g = lane >> 2;
        int u = nt * 8 + g;
        const float* wr = ((u < 128) ? (W1a + u * 192) : (W1g + (u - 128) * 192)) + 64 + grp * 16;
        g_B1h[id] = make_uint2(packh2(wr[2*t], wr[2*t+1]), packh2(wr[2*t+8], wr[2*t+9]));
    } else if (id < 12288) {                          // B2h: +W2a / -W2g (K = ua..128, ug..256)
        int i = id - 8192;
        int grpG = i >> 8, rem = i & 255;
        int nt = rem >> 5, lane = rem & 31;
        int t = lane & 3, g = lane >> 2;
        int o = nt * 8 + g;
        if (grpG < 8) {
            const float* wr = W2a + o * 128 + grpG * 16;
            g_B2h[i] = make_uint2(packh2(wr[2*t], wr[2*t+1]), packh2(wr[2*t+8], wr[2*t+9]));
        } else {
            const float* wr = W2g + o * 128 + (grpG - 8) * 16;
            g_B2h[i] = make_uint2(packh2(-wr[2*t], -wr[2*t+1]), packh2(-wr[2*t+8], -wr[2*t+9]));
        }
    } else if (id < 24576) {                          // B3h: Whh[j][k]
        int i = id - 12288;
        int grp = i / 1536, rem = i % 1536;
        int nt = rem >> 5, lane = rem & 31;
        int t = lane & 3, g = lane >> 2;
        int j = nt * 8 + g;
        const float* wr = Whh + j * 128 + grp * 16;
        g_B3h[i] = make_uint2(packh2(wr[2*t], wr[2*t+1]), packh2(wr[2*t+8], wr[2*t+9]));
    } else if (id < 30720) {                          // B4h: Wih[j][k], k<64
        int i = id - 24576;
        int grp = i / 1536, rem = i % 1536;
        int nt = rem >> 5, lane = rem & 31;
        int t = lane & 3, g = lane >> 2;
        int j = nt * 8 + g;
        const float* wr = Wih + j * 65 + grp * 16;
        g_B4h[i] = make_uint2(packh2(wr[2*t], wr[2*t+1]), packh2(wr[2*t+8], wr[2*t+9]));
    } else if (id < 30976) {                          // xc (exact fp32 x-fold)
        int u = id - 30720;
        const float* W = (u < 128) ? W1a : W1g;
        const float* b = (u < 128) ? b1a : b1g;
        int j = u & 127;
        float s = b[j];
        const float* row = W + j * 192;
        #pragma unroll 8
        for (int k = 0; k < 64; k++) s += row[k] * x[k];
        g_xc[u] = s;
    } else if (id < 31040) {
        int o = id - 30976;
        g_b2d[o] = b2a[o] - b2g[o];
    } else if (id < 31424) {
        int j = id - 31040;
        g_wt[j] = Wih[j * 65 + 64];
    } else if (id < 31680) {
        int j = id - 31424;
        g_brz[j] = bih[j] + bhh[j];
    } else if (id < 31808) {
        int j = id - 31680;
        g_bni[j] = bih[256 + j];
    } else if (id < 31936) {
        int j = id - 31808;
        g_bnh[j] = bhh[256 + j];
    }
}

// ---------------- Kernel B: fused per-cell pipeline (fp16 tensor cores) ----------------
__global__ __launch_bounds__(512, 1) void kB(
    const float* __restrict__ hiddens,
    float* __restrict__ dout)
{
    extern __shared__ float sm[];
    float*  h_s   = sm + OFF_H;
    __half* h_h   = (__half*)(sm + OFF_HH);
    __half* c1h   = (__half*)(sm + OFF_C1H);
    __half* outh  = (__half*)(sm + OFF_OUTH);
    float*  P0    = sm + OFF_P0;
    float*  P1    = sm + OFF_P1;
    float*  t_s   = sm + OFF_T;
    float*  e_s   = sm + OFF_E;
    float*  xc_s  = sm + OFF_XC;
    float*  b2d_s = sm + OFF_B2D;
    float*  brz_s = sm + OFF_BRZ;
    float*  bni_s = sm + OFF_BNI;
    float*  bnh_s = sm + OFF_BNH;
    float*  wt_s  = sm + OFF_WT;

    const int tid  = threadIdx.x;
    const int blk  = blockIdx.x;
    const int w    = tid >> 5;
    const int lane = tid & 31;
    const int t4   = lane & 3;      // tig
    const int g    = lane >> 2;     // groupID

    // ---- stage 0: load h tile (fp32 + half2 copies) + constant tables ----
    const float* H = hiddens + (size_t)blk * MT * 128;
    #pragma unroll
    for (int i = tid; i < MT * 32; i += TPB) {
        float4 v = ((const float4*)H)[i];
        int c = i >> 5, k = (i & 31) << 2;
        float* p = h_s + c * HP + k;
        p[0] = v.x; p[1] = v.y; p[2] = v.z; p[3] = v.w;
        unsigned* q = (unsigned*)(h_h + c * HHP + k);
        q[0] = packh2(v.x, v.y);
        q[1] = packh2(v.z, v.w);
    }
    if (tid < 256) { xc_s[tid] = g_xc[tid]; brz_s[tid] = g_brz[tid]; }
    if (tid < 64)  { b2d_s[tid] = g_b2d[tid]; }
    if (tid < 128) { bni_s[tid] = g_bni[tid]; bnh_s[tid] = g_bnh[tid]; }
    if (tid < 384) { wt_s[tid] = g_wt[tid]; }
    __syncthreads();

    // ---- stage 1: C1[64x256] = relu(h @ B1 + xc); warp owns 16 cols, loops 4 m-tiles ----
    {
        float acc[4][2][4];
        #pragma unroll
        for (int m = 0; m < 4; m++)
            #pragma unroll
            for (int n = 0; n < 2; n++)
                #pragma unroll
                for (int cidx = 0; cidx < 4; cidx++) acc[m][n][cidx] = 0.f;
        #pragma unroll
        for (int grp = 0; grp < 8; grp++) {
            uint2 bv0 = g_B1h[(grp * 32 + 2 * w)     * 32 + lane];
            uint2 bv1 = g_B1h[(grp * 32 + 2 * w + 1) * 32 + lane];
            #pragma unroll
            for (int m = 0; m < 4; m++) {
                int r0 = m * 16 + g, r1 = r0 + 8;
                const unsigned* p0 = (const unsigned*)(h_h + r0 * HHP + grp * 16 + 2 * t4);
                const unsigned* p1 = (const unsigned*)(h_h + r1 * HHP + grp * 16 + 2 * t4);
                unsigned a0 = p0[0], a1 = p1[0], a2 = p0[4], a3 = p1[4];
                mma16(acc[m][0], a0, a1, a2, a3, bv0.x, bv0.y);
                mma16(acc[m][1], a0, a1, a2, a3, bv1.x, bv1.y);
            }
        }
        #pragma unroll
        for (int m = 0; m < 4; m++) {
            int r0 = m * 16 + g, r1 = r0 + 8;
            #pragma unroll
            for (int n = 0; n < 2; n++) {
                int cb = w * 16 + n * 8 + 2 * t4;
                float x0 = xc_s[cb], x1 = xc_s[cb + 1];
                *(unsigned*)(c1h + r0 * C1HP + cb) =
                    packh2(fmaxf(acc[m][n][0] + x0, 0.f), fmaxf(acc[m][n][1] + x1, 0.f));
                *(unsigned*)(c1h + r1 * C1HP + cb) =
                    packh2(fmaxf(acc[m][n][2] + x0, 0.f), fmaxf(acc[m][n][3] + x1, 0.f));
            }
        }
    }
    __syncthreads();

    // ---- stage 2: out = C1 @ B2 + b2d, split-K over 2 warp groups ----
    {
        const int nt = w & 7, kh = w >> 3;
        float acc[4][4];
        #pragma unroll
        for (int m = 0; m < 4; m++)
            #pragma unroll
            for (int cidx = 0; cidx < 4; cidx++) acc[m][cidx] = 0.f;
        #pragma unroll
        for (int grp = 0; grp < 8; grp++) {
            int grpG = kh * 8 + grp;
            uint2 bv = g_B2h[(grpG * 8 + nt) * 32 + lane];
            #pragma unroll
            for (int m = 0; m < 4; m++) {
                int r0 = m * 16 + g, r1 = r0 + 8;
                const unsigned* p0 = (const unsigned*)(c1h + r0 * C1HP + grpG * 16 + 2 * t4);
                const unsigned* p1 = (const unsigned*)(c1h + r1 * C1HP + grpG * 16 + 2 * t4);
                mma16(acc[m], p0[0], p1[0], p0[4], p1[4], bv.x, bv.y);
            }
        }
        float* P = kh ? P1 : P0;
        #pragma unroll
        for (int m = 0; m < 4; m++) {
            int r0 = m * 16 + g, r1 = r0 + 8;
            int o = nt * 8 + 2 * t4;
            float x0 = kh ? 0.f : b2d_s[o], x1 = kh ? 0.f : b2d_s[o + 1];
            P[r0 * PP + o]     = acc[m][0] + x0;
            P[r0 * PP + o + 1] = acc[m][1] + x1;
            P[r1 * PP + o]     = acc[m][2] + x0;
            P[r1 * PP + o + 1] = acc[m][3] + x1;
        }
    }
    __syncthreads();

    // ---- merge split-K partials -> out_h (half2) ----
    #pragma unroll
    for (int i = 0; i < 4; i++) {
        int idx = tid + i * TPB;               // 2048 half2 words
        int row = idx >> 5, cp = (idx & 31) << 1;
        float s0 = P0[row * PP + cp]     + P1[row * PP + cp];
        float s1 = P0[row * PP + cp + 1] + P1[row * PP + cp + 1];
        *(unsigned*)(outh + row * OHP + cp) = packh2(s0, s1);
    }
    __syncthreads();

    // ---- t/e (warps 0-1) concurrent with GRU mma ----
    if (tid < 64) {
        const unsigned* orow = (const unsigned*)(outh + tid * OHP);
        float s = 0.f;
        #pragma unroll
        for (int c = 0; c < 32; c++) {
            __half2 hv = *(const __half2*)(orow + c);
            float2 f = __half22float2(hv);
            s += f.x * f.x + f.y * f.y;
        }
        float tt = s * (1.f / 64.f);
        t_s[tid] = tt;
        e_s[tid] = expf(tt);
    }

    // ---- GRU: warp owns j-slice [w*8, w*8+8), loops 4 m-tiles ----
    float aR[4][4], aZ[4][4], aNh[4][4], aNi[4][4];
    {
        #pragma unroll
        for (int m = 0; m < 4; m++)
            #pragma unroll
            for (int cidx = 0; cidx < 4; cidx++)
                { aR[m][cidx] = 0.f; aZ[m][cidx] = 0.f; aNh[m][cidx] = 0.f; aNi[m][cidx] = 0.f; }

        // h-side: K=128 over h_h
        #pragma unroll
        for (int grp = 0; grp < 8; grp++) {
            uint2 bR = g_B3h[(grp * 48 + w)      * 32 + lane];
            uint2 bZ = g_B3h[(grp * 48 + 16 + w) * 32 + lane];
            uint2 bN = g_B3h[(grp * 48 + 32 + w) * 32 + lane];
            #pragma unroll
            for (int m = 0; m < 4; m++) {
                int r0 = m * 16 + g, r1 = r0 + 8;
                const unsigned* p0 = (const unsigned*)(h_h + r0 * HHP + grp * 16 + 2 * t4);
                const unsigned* p1 = (const unsigned*)(h_h + r1 * HHP + grp * 16 + 2 * t4);
                unsigned a0 = p0[0], a1 = p1[0], a2 = p0[4], a3 = p1[4];
                mma16(aR[m],  a0, a1, a2, a3, bR.x, bR.y);
                mma16(aZ[m],  a0, a1, a2, a3, bZ.x, bZ.y);
                mma16(aNh[m], a0, a1, a2, a3, bN.x, bN.y);
            }
        }
        // i-side: K=64 over out_h (r,z accumulate on; n separate)
        #pragma unroll
        for (int grp = 0; grp < 4; grp++) {
            uint2 bR = g_B4h[(grp * 48 + w)      * 32 + lane];
            uint2 bZ = g_B4h[(grp * 48 + 16 + w) * 32 + lane];
            uint2 bN = g_B4h[(grp * 48 + 32 + w) * 32 + lane];
            #pragma unroll
            for (int m = 0; m < 4; m++) {
                int r0 = m * 16 + g, r1 = r0 + 8;
                const unsigned* p0 = (const unsigned*)(outh + r0 * OHP + grp * 16 + 2 * t4);
                const unsigned* p1 = (const unsigned*)(outh + r1 * OHP + grp * 16 + 2 * t4);
                unsigned a0 = p0[0], a1 = p1[0], a2 = p0[4], a3 = p1[4];
                mma16(aR[m],  a0, a1, a2, a3, bR.x, bR.y);
                mma16(aZ[m],  a0, a1, a2, a3, bZ.x, bZ.y);
                mma16(aNi[m], a0, a1, a2, a3, bN.x, bN.y);
            }
        }
    }
    __syncthreads();   // t_s/e_s ready; all out_h/h_h reads complete

    // ---- GRU elementwise epilogue (writes nh into h_s in place) ----
    {
        int j0 = w * 8 + 2 * t4;
        float brzr0 = brz_s[j0],       brzr1 = brz_s[j0 + 1];
        float brzz0 = brz_s[128 + j0], brzz1 = brz_s[128 + j0 + 1];
        float bni0  = bni_s[j0],       bni1  = bni_s[j0 + 1];
        float bnh0  = bnh_s[j0],       bnh1  = bnh_s[j0 + 1];
        float wtr0 = wt_s[j0],        wtr1 = wt_s[j0 + 1];
        float wtz0 = wt_s[128 + j0],  wtz1 = wt_s[128 + j0 + 1];
        float wtn0 = wt_s[256 + j0],  wtn1 = wt_s[256 + j0 + 1];
        #pragma unroll
        for (int m = 0; m < 4; m++) {
            int r0 = m * 16 + g, r1 = r0 + 8;
            float tv0 = t_s[r0], tv1 = t_s[r1];
            // (row r0, col j0) -> acc idx 0 ; (r0, j0+1) -> 1 ; (r1, j0) -> 2 ; (r1, j0+1) -> 3
            {
                float r = sigmoid_f(aR[m][0] + brzr0 + tv0 * wtr0);
                float z = sigmoid_f(aZ[m][0] + brzz0 + tv0 * wtz0);
                float n = tanhf(aNi[m][0] + tv0 * wtn0 + bni0 + r * (aNh[m][0] + bnh0));
                float hv = h_s[r0 * HP + j0];
                h_s[r0 * HP + j0] = (1.f - z) * n + z * hv;
            }
            {
                float r = sigmoid_f(aR[m][1] + brzr1 + tv0 * wtr1);
                float z = sigmoid_f(aZ[m][1] + brzz1 + tv0 * wtz1);
                float n = tanhf(aNi[m][1] + tv0 * wtn1 + bni1 + r * (aNh[m][1] + bnh1));
                float hv = h_s[r0 * HP + j0 + 1];
                h_s[r0 * HP + j0 + 1] = (1.f - z) * n + z * hv;
            }
            {
                float r = sigmoid_f(aR[m][2] + brzr0 + tv1 * wtr0);
                float z = sigmoid_f(aZ[m][2] + brzz0 + tv1 * wtz0);
                float n = tanhf(aNi[m][2] + tv1 * wtn0 + bni0 + r * (aNh[m][2] + bnh0));
                float hv = h_s[r1 * HP + j0];
                h_s[r1 * HP + j0] = (1.f - z) * n + z * hv;
            }
            {
                float r = sigmoid_f(aR[m][3] + brzr1 + tv1 * wtr1);
                float z = sigmoid_f(aZ[m][3] + brzz1 + tv1 * wtz1);
                float n = tanhf(aNi[m][3] + tv1 * wtn1 + bni1 + r * (aNh[m][3] + bnh1));
                float hv = h_s[r1 * HP + j0 + 1];
                h_s[r1 * HP + j0 + 1] = (1.f - z) * n + z * hv;
            }
        }
    }
    __syncthreads();

    // ---- store new_h (pre-sync) coalesced; block partials ----
    float* NH = dout + 65 + (size_t)blk * MT * 128;
    #pragma unroll
    for (int i = tid; i < MT * 128; i += TPB) {
        int c = i >> 7, k = i & 127;
        NH[i] = h_s[c * HP + k];
    }
    if (tid < 128) {
        float s = 0.f;
        #pragma unroll 8
        for (int c = 0; c < 64; c++) s += h_s[c * HP + tid];
        g_blk_h[(size_t)blk * 128 + tid] = s;
    }
    if (tid < 64) {
        float s = 0.f;
        #pragma unroll 8
        for (int c = 0; c < 64; c++) s += e_s[c] * __half2float(outh[c * OHP + tid]);
        g_blk_wout[(size_t)blk * 64 + tid] = s;
    } else if (tid == 64) {
        float s = 0.f;
        for (int c = 0; c < 64; c++) s += t_s[c];
        g_blk_t[blk] = s;
    } else if (tid == 96) {
        float s = 0.f;
        for (int c = 0; c < 64; c++) s += e_s[c];
        g_blk_e[blk] = s;
    }
}

// ---------------- Kernel C: global reductions + head ----------------
__global__ __launch_bounds__(1024) void kC(
    const float* __restrict__ Wo, const float* __restrict__ bo,
    float* __restrict__ dout)
{
    __shared__ float s_red[1024];
    __shared__ float s_red2[1024];
    __shared__ float s_comb[64];
    __shared__ float s_esum;
    const int tid = threadIdx.x;

    {
        int f = tid >> 7, j = tid & 127;
        const float* p = g_blk_h + (size_t)(f * 256) * 128 + j;
        float s = 0.f;
        #pragma unroll 8
        for (int b = 0; b < 256; b++) s += p[b * 128];
        g_fm[f * 128 + j] = s * (1.f / 16384.f);
        s_red[tid] = s;
    }
    __syncthreads();
    if (tid < 128) {
        float gg = 0.f;
        #pragma unroll
        for (int f = 0; f < 8; f++) gg += s_red[f * 128 + tid];
        g_go[tid] = gg * (1.f / (float)NCELLS);
    }
    __syncthreads();

    {
        int o = tid & 63, ch = tid >> 6;
        const float* p = g_blk_wout + (size_t)(ch * 128) * 64 + o;
        float s = 0.f;
        #pragma unroll 8
        for (int b = 0; b < 128; b++) s += p[b * 64];
        s_red[tid] = s;
    }
    __syncthreads();
    if (tid < 64) {
        float s = 0.f;
        #pragma unroll
        for (int ch = 0; ch < 16; ch++) s += s_red[ch * 64 + tid];
        s_comb[tid] = s;
    }
    __syncthreads();

    float se = 0.f, st = 0.f;
    for (int i = tid; i < NBLK; i += 1024) { se += g_blk_e[i]; st += g_blk_t[i]; }
    s_red[tid] = se;
    s_red2[tid] = st;
    __syncthreads();
    for (int off = 512; off > 0; off >>= 1) {
        if (tid < off) { s_red[tid] += s_red[tid + off]; s_red2[tid] += s_red2[tid + off]; }
        __syncthreads();
    }
    if (tid == 0) {
        s_esum = s_red[0];
        dout[64] = s_red2[0] * (1.f / (float)NCELLS);
    }
    __syncthreads();

    if (tid < 64) s_comb[tid] *= (1.f / s_esum);
    __syncthreads();
    if (tid < 64) {
        float p = bo[tid];
        const float* wr = Wo + tid * 64;
        #pragma unroll 8
        for (int o = 0; o < 64; o++) p += wr[o] * s_comb[o];
        dout[tid] = p;
    }
}

// ---------------- Kernel D: faction sync (in-place on d_out new_h) ----------------
__global__ __launch_bounds__(512) void kD(float* __restrict__ nh, const void* __restrict__ stepPtr)
{
    int iv = *(const int*)stepPtr;
    int step = (iv >= 0 && iv < 1000000) ? iv : (int)(*(const float*)stepPtr);
    const bool debate = (step > 5);

    unsigned base = blockIdx.x * 512u + threadIdx.x;
    const unsigned stride = 2048u * 512u;
    #pragma unroll 4
    for (int r = 0; r < 16; r++) {
        unsigned e = base + (unsigned)r * stride;
        unsigned cell = e >> 7;
        unsigned j = e & 127u;
        unsigned f = cell >> 14;
        unsigned pos = cell & 16383u;
        float v = nh[e];
        v = 0.85f * v + 0.15f * g_fm[f * 128 + j];
        if (debate && pos < 4096u) v = 0.85f * v + 0.15f * g_go[j];
        nh[e] = v;
    }
}

// ---------------- launcher ----------------
extern "C" void kernel_launch(void* const* d_in, const int* in_sizes, int n_in,
                              void* d_out, int out_size)
{
    const float* x    = (const float*)d_in[0];
    const float* hid  = (const float*)d_in[1];
    const float* W1a  = (const float*)d_in[2];
    const float* b1a  = (const float*)d_in[3];
    const float* W2a  = (const float*)d_in[4];
    const float* b2a  = (const float*)d_in[5];
    const float* W1g  = (const float*)d_in[6];
    const float* b1g  = (const float*)d_in[7];
    const float* W2g  = (const float*)d_in[8];
    const float* b2g  = (const float*)d_in[9];
    const float* Wih  = (const float*)d_in[10];
    const float* Whh  = (const float*)d_in[11];
    const float* bih  = (const float*)d_in[12];
    const float* bhh  = (const float*)d_in[13];
    const float* Wo   = (const float*)d_in[14];
    const float* bo   = (const float*)d_in[15];
    const void*  step = (n_in > 16) ? (const void*)d_in[16] : (const void*)d_in[15];

    float* out = (float*)d_out;
    float* nh  = out + 65;

    cudaFuncSetAttribute(kB, cudaFuncAttributeMaxDynamicSharedMemorySize, SMEM_KB_BYTES);

    kA<<<63, 512>>>(x, W1a, b1a, W1g, b1g, b2a, b2g, W2a, W2g, Wih, Whh, bih, bhh);
    kB<<<NBLK, TPB, SMEM_KB_BYTES>>>(hid, out);
    kC<<<1, 1024>>>(Wo, bo, out);
    kD<<<2048, 512>>>(nh, step);
}

// round 9
// speedup vs baseline: 6.8486x; 1.0905x over previous
#include <cuda_runtime.h>
#include <cuda_fp16.h>
#include <stdint.h>
#include <math.h>

// ---------------- problem constants ----------------
#define NCELLS 131072
#define MT   128
#define TPB  512
#define NBLK (NCELLS / MT)   // 1024

// ---------------- smem layout (float offsets) ----------------
#define HHP   136            // h_h half pitch
#define C1HP  264            // C1h half pitch
#define OHP   72             // out_h half pitch
#define NHP   132            // nh fp32 pitch (aliases C1 region)

#define OFF_HH   0                        // 128*136 h = 8704 floats
#define OFF_C1H  8704                     // 128*264 h = 16896 floats (aliased by nh fp32 128*132)
#define OFF_OUTH 25600                    // 128*72 h  = 4608 floats
#define OFF_T    30208                    // 128
#define OFF_E    30336                    // 128
#define OFF_XC   30464                    // 256
#define OFF_B2D  30720                    // 64
#define OFF_BRZ  30784                    // 256
#define OFF_BNI  31040                    // 128
#define OFF_BNH  31168                    // 128
#define OFF_WT   31296                    // 384
#define SMEM_KB_FLOATS 31680
#define SMEM_KB_BYTES  (SMEM_KB_FLOATS * 4)   // 126720 B

// ---------------- device scratch (static, allocation-free) ----------------
__device__ uint2 g_B1h[8 * 32 * 32];     // stage1  K=128,N=256
__device__ uint2 g_B2h[16 * 8 * 32];     // stage2  K=256,N=64 (sign-folded)
__device__ uint2 g_B3h[8 * 48 * 32];     // GRU Whh K=128,N=384
__device__ uint2 g_B4h[4 * 48 * 32];     // GRU Wih K=64, N=384
__device__ float g_xc[256];
__device__ float g_b2d[64];
__device__ float g_brz[256];
__device__ float g_bni[128];
__device__ float g_bnh[128];
__device__ float g_wt[384];
__device__ float g_blk_t[NBLK];
__device__ float g_blk_e[NBLK];
__device__ float g_blk_wout[NBLK * 64];
__device__ float g_blk_h[NBLK * 128];
__device__ float g_fm[8 * 128];
__device__ float g_go[128];

// ---------------- helpers ----------------
__device__ __forceinline__ unsigned packh2(float lo, float hi) {
    __half2 h = __floats2half2_rn(lo, hi);
    return *(unsigned*)&h;
}
__device__ __forceinline__ void mma16(float* c,
    unsigned a0, unsigned a1, unsigned a2, unsigned a3,
    unsigned b0, unsigned b1)
{
    asm volatile(
        "mma.sync.aligned.m16n8k16.row.col.f32.f16.f16.f32 "
        "{%0,%1,%2,%3},{%4,%5,%6,%7},{%8,%9},{%0,%1,%2,%3};"
        : "+f"(c[0]), "+f"(c[1]), "+f"(c[2]), "+f"(c[3])
        : "r"(a0), "r"(a1), "r"(a2), "r"(a3), "r"(b0), "r"(b1));
}
__device__ __forceinline__ float sigmoid_f(float x) {
    return 1.f / (1.f + __expf(-x));
}

// ---------------- kA1: pack B1h + B2h ----------------
__global__ __launch_bounds__(512) void kA1(
    const float* __restrict__ W1a, const float* __restrict__ W1g,
    const float* __restrict__ W2a, const float* __restrict__ W2g)
{
    int id = blockIdx.x * 512 + threadIdx.x;
    if (id < 8192) {                                  // B1h: B[k][u]=W1[u][64+k]
        int grp = id >> 10, rem = id & 1023;
        int nt = rem >> 5, lane = rem & 31;
        int t = lane & 3, g = lane >> 2;
        int u = nt * 8 + g;
        const float* wr = ((u < 128) ? (W1a + u * 192) : (W1g + (u - 128) * 192)) + 64 + grp * 16;
        g_B1h[id] = make_uint2(packh2(wr[2*t], wr[2*t+1]), packh2(wr[2*t+8], wr[2*t+9]));
    } else if (id < 12288) {                          // B2h: +W2a / -W2g
        int i = id - 8192;
        int grpG = i >> 8, rem = i & 255;
        int nt = rem >> 5, lane = rem & 31;
        int t = lane & 3, g = lane >> 2;
        int o = nt * 8 + g;
        if (grpG < 8) {
            const float* wr = W2a + o * 128 + grpG * 16;
            g_B2h[i] = make_uint2(packh2(wr[2*t], wr[2*t+1]), packh2(wr[2*t+8], wr[2*t+9]));
        } else {
            const float* wr = W2g + o * 128 + (grpG - 8) * 16;
            g_B2h[i] = make_uint2(packh2(-wr[2*t], -wr[2*t+1]), packh2(-wr[2*t+8], -wr[2*t+9]));
        }
    }
}

// ---------------- kA2: pack B3h + B4h ----------------
__global__ __launch_bounds__(512) void kA2(
    const float* __restrict__ Wih, const float* __restrict__ Whh)
{
    int id = blockIdx.x * 512 + threadIdx.x;
    if (id < 12288) {                                 // B3h: Whh[j][k]
        int grp = id / 1536, rem = id % 1536;
        int nt = rem >> 5, lane = rem & 31;
        int t = lane & 3, g = lane >> 2;
        int j = nt * 8 + g;
        const float* wr = Whh + j * 128 + grp * 16;
        g_B3h[id] = make_uint2(packh2(wr[2*t], wr[2*t+1]), packh2(wr[2*t+8], wr[2*t+9]));
    } else if (id < 18432) {                          // B4h: Wih[j][k], k<64
        int i = id - 12288;
        int grp = i / 1536, rem = i % 1536;
        int nt = rem >> 5, lane = rem & 31;
        int t = lane & 3, g = lane >> 2;
        int j = nt * 8 + g;
        const float* wr = Wih + j * 65 + grp * 16;
        g_B4h[i] = make_uint2(packh2(wr[2*t], wr[2*t+1]), packh2(wr[2*t+8], wr[2*t+9]));
    }
}

// ---------------- kA3: misc vectors ----------------
__global__ __launch_bounds__(512) void kA3(
    const float* __restrict__ x,
    const float* __restrict__ W1a, const float* __restrict__ b1a,
    const float* __restrict__ W1g, const float* __restrict__ b1g,
    const float* __restrict__ b2a, const float* __restrict__ b2g,
    const float* __restrict__ Wih,
    const float* __restrict__ bih, const float* __restrict__ bhh)
{
    int id = blockIdx.x * 512 + threadIdx.x;
    if (id < 256) {                                   // xc (exact fp32 x-fold)
        const float* W = (id < 128) ? W1a : W1g;
        const float* b = (id < 128) ? b1a : b1g;
        int j = id & 127;
        float s = b[j];
        const float* row = W + j * 192;
        #pragma unroll 8
        for (int k = 0; k < 64; k++) s += row[k] * x[k];
        g_xc[id] = s;
    } else if (id < 320) {
        int o = id - 256;
        g_b2d[o] = b2a[o] - b2g[o];
    } else if (id < 704) {
        int j = id - 320;
        g_wt[j] = Wih[j * 65 + 64];
    } else if (id < 960) {
        int j = id - 704;
        g_brz[j] = bih[j] + bhh[j];
    } else if (id < 1088) {
        int j = id - 960;
        g_bni[j] = bih[256 + j];
    } else if (id < 1216) {
        int j = id - 1088;
        g_bnh[j] = bhh[256 + j];
    }
}

// ---------------- Kernel B: fused per-cell pipeline (fp16 MMA, 128 cells/block) ----------------
__global__ __launch_bounds__(512, 1) void kB(
    const float* __restrict__ hiddens,
    float* __restrict__ dout)
{
    extern __shared__ float sm[];
    __half* h_h   = (__half*)(sm + OFF_HH);
    __half* c1h   = (__half*)(sm + OFF_C1H);
    float*  nh_s  = sm + OFF_C1H;        // aliases c1h after stage 2
    __half* outh  = (__half*)(sm + OFF_OUTH);
    float*  t_s   = sm + OFF_T;
    float*  e_s   = sm + OFF_E;
    float*  xc_s  = sm + OFF_XC;
    float*  b2d_s = sm + OFF_B2D;
    float*  brz_s = sm + OFF_BRZ;
    float*  bni_s = sm + OFF_BNI;
    float*  bnh_s = sm + OFF_BNH;
    float*  wt_s  = sm + OFF_WT;

    const int tid  = threadIdx.x;
    const int blk  = blockIdx.x;
    const int w    = tid >> 5;
    const int lane = tid & 31;
    const int t4   = lane & 3;
    const int g    = lane >> 2;

    const float* Hg = hiddens + (size_t)blk * MT * 128;

    // ---- stage 0: load h tile (fp16) + constant tables ----
    #pragma unroll
    for (int i = tid; i < MT * 32; i += TPB) {       // 4096 float4
        float4 v = ((const float4*)Hg)[i];
        int c = i >> 5, k = (i & 31) << 2;
        unsigned* q = (unsigned*)(h_h + c * HHP + k);
        q[0] = packh2(v.x, v.y);
        q[1] = packh2(v.z, v.w);
    }
    if (tid < 256) { xc_s[tid] = g_xc[tid]; brz_s[tid] = g_brz[tid]; }
    if (tid < 64)  { b2d_s[tid] = g_b2d[tid]; }
    if (tid < 128) { bni_s[tid] = g_bni[tid]; bnh_s[tid] = g_bnh[tid]; }
    if (tid < 384) { wt_s[tid] = g_wt[tid]; }
    __syncthreads();

    // ---- stage 1: C1[128x256] = relu(h @ B1 + xc); warp owns 16 cols, loops 8 m-tiles ----
    {
        float acc[8][2][4];
        #pragma unroll
        for (int m = 0; m < 8; m++)
            #pragma unroll
            for (int n = 0; n < 2; n++)
                #pragma unroll
                for (int c = 0; c < 4; c++) acc[m][n][c] = 0.f;
        #pragma unroll
        for (int grp = 0; grp < 8; grp++) {
            uint2 bv0 = g_B1h[(grp * 32 + 2 * w)     * 32 + lane];
            uint2 bv1 = g_B1h[(grp * 32 + 2 * w + 1) * 32 + lane];
            #pragma unroll
            for (int m = 0; m < 8; m++) {
                int r0 = m * 16 + g, r1 = r0 + 8;
                const unsigned* p0 = (const unsigned*)(h_h + r0 * HHP + grp * 16 + 2 * t4);
                const unsigned* p1 = (const unsigned*)(h_h + r1 * HHP + grp * 16 + 2 * t4);
                unsigned a0 = p0[0], a1 = p1[0], a2 = p0[4], a3 = p1[4];
                mma16(acc[m][0], a0, a1, a2, a3, bv0.x, bv0.y);
                mma16(acc[m][1], a0, a1, a2, a3, bv1.x, bv1.y);
            }
        }
        #pragma unroll
        for (int m = 0; m < 8; m++) {
            int r0 = m * 16 + g, r1 = r0 + 8;
            #pragma unroll
            for (int n = 0; n < 2; n++) {
                int cb = w * 16 + n * 8 + 2 * t4;
                float x0 = xc_s[cb], x1 = xc_s[cb + 1];
                *(unsigned*)(c1h + r0 * C1HP + cb) =
                    packh2(fmaxf(acc[m][n][0] + x0, 0.f), fmaxf(acc[m][n][1] + x1, 0.f));
                *(unsigned*)(c1h + r1 * C1HP + cb) =
                    packh2(fmaxf(acc[m][n][2] + x0, 0.f), fmaxf(acc[m][n][3] + x1, 0.f));
            }
        }
    }
    __syncthreads();

    // ---- stage 2: out[128x64] = C1 @ B2 + b2d; warp: n-tile (w&7), m-half (w>>3), K=256 full ----
    {
        const int nt = w & 7, mh = w >> 3;
        float acc[4][4];
        #pragma unroll
        for (int m = 0; m < 4; m++)
            #pragma unroll
            for (int c = 0; c < 4; c++) acc[m][c] = 0.f;
        #pragma unroll
        for (int grpG = 0; grpG < 16; grpG++) {
            uint2 bv = g_B2h[(grpG * 8 + nt) * 32 + lane];
            #pragma unroll
            for (int mi = 0; mi < 4; mi++) {
                int r0 = (mh * 4 + mi) * 16 + g, r1 = r0 + 8;
                const unsigned* p0 = (const unsigned*)(c1h + r0 * C1HP + grpG * 16 + 2 * t4);
                const unsigned* p1 = (const unsigned*)(c1h + r1 * C1HP + grpG * 16 + 2 * t4);
                mma16(acc[mi], p0[0], p1[0], p0[4], p1[4], bv.x, bv.y);
            }
        }
        int o = nt * 8 + 2 * t4;
        float x0 = b2d_s[o], x1 = b2d_s[o + 1];
        #pragma unroll
        for (int mi = 0; mi < 4; mi++) {
            int r0 = (mh * 4 + mi) * 16 + g, r1 = r0 + 8;
            *(unsigned*)(outh + r0 * OHP + o) = packh2(acc[mi][0] + x0, acc[mi][1] + x1);
            *(unsigned*)(outh + r1 * OHP + o) = packh2(acc[mi][2] + x0, acc[mi][3] + x1);
        }
    }
    __syncthreads();

    // ---- t/e (tid<128) — overlapped with GRU pass-1 mma of all warps ----
    if (tid < 128) {
        const unsigned* orow = (const unsigned*)(outh + tid * OHP);
        float s = 0.f;
        #pragma unroll
        for (int c = 0; c < 32; c++) {
            float2 f = __half22float2(*(const __half2*)(orow + c));
            s += f.x * f.x + f.y * f.y;
        }
        float tt = s * (1.f / 64.f);
        t_s[tid] = tt;
        e_s[tid] = expf(tt);
    }

    // ---- GRU: warp owns j-slice [w*8,(w+1)*8), two m-half passes ----
    #pragma unroll 1
    for (int mh = 0; mh < 2; mh++) {
        float aR[4][4], aZ[4][4], aNh[4][4], aNi[4][4];
        #pragma unroll
        for (int m = 0; m < 4; m++)
            #pragma unroll
            for (int c = 0; c < 4; c++)
                { aR[m][c] = 0.f; aZ[m][c] = 0.f; aNh[m][c] = 0.f; aNi[m][c] = 0.f; }

        // h-side (K=128)
        #pragma unroll
        for (int grp = 0; grp < 8; grp++) {
            uint2 bR = g_B3h[(grp * 48 + w)      * 32 + lane];
            uint2 bZ = g_B3h[(grp * 48 + 16 + w) * 32 + lane];
            uint2 bN = g_B3h[(grp * 48 + 32 + w) * 32 + lane];
            #pragma unroll
            for (int mi = 0; mi < 4; mi++) {
                int r0 = (mh * 4 + mi) * 16 + g, r1 = r0 + 8;
                const unsigned* p0 = (const unsigned*)(h_h + r0 * HHP + grp * 16 + 2 * t4);
                const unsigned* p1 = (const unsigned*)(h_h + r1 * HHP + grp * 16 + 2 * t4);
                unsigned a0 = p0[0], a1 = p1[0], a2 = p0[4], a3 = p1[4];
                mma16(aR[mi],  a0, a1, a2, a3, bR.x, bR.y);
                mma16(aZ[mi],  a0, a1, a2, a3, bZ.x, bZ.y);
                mma16(aNh[mi], a0, a1, a2, a3, bN.x, bN.y);
            }
        }
        // i-side (K=64)
        #pragma unroll
        for (int grp = 0; grp < 4; grp++) {
            uint2 bR = g_B4h[(grp * 48 + w)      * 32 + lane];
            uint2 bZ = g_B4h[(grp * 48 + 16 + w) * 32 + lane];
            uint2 bN = g_B4h[(grp * 48 + 32 + w) * 32 + lane];
            #pragma unroll
            for (int mi = 0; mi < 4; mi++) {
                int r0 = (mh * 4 + mi) * 16 + g, r1 = r0 + 8;
                const unsigned* p0 = (const unsigned*)(outh + r0 * OHP + grp * 16 + 2 * t4);
                const unsigned* p1 = (const unsigned*)(outh + r1 * OHP + grp * 16 + 2 * t4);
                unsigned a0 = p0[0], a1 = p1[0], a2 = p0[4], a3 = p1[4];
                mma16(aR[mi],  a0, a1, a2, a3, bR.x, bR.y);
                mma16(aZ[mi],  a0, a1, a2, a3, bZ.x, bZ.y);
                mma16(aNi[mi], a0, a1, a2, a3, bN.x, bN.y);
            }
        }

        if (mh == 0) __syncthreads();   // t_s/e_s ready; stage-2 c1h reads complete -> nh alias safe

        // epilogue: nh into staging (c1h alias); exact fp32 h re-read from global (L2-hot)
        {
            int j0 = w * 8 + 2 * t4;
            float brzr0 = brz_s[j0],       brzr1 = brz_s[j0 + 1];
            float brzz0 = brz_s[128 + j0], brzz1 = brz_s[128 + j0 + 1];
            float bni0  = bni_s[j0],       bni1  = bni_s[j0 + 1];
            float bnh0  = bnh_s[j0],       bnh1  = bnh_s[j0 + 1];
            float wtr0 = wt_s[j0],        wtr1 = wt_s[j0 + 1];
            float wtz0 = wt_s[128 + j0],  wtz1 = wt_s[128 + j0 + 1];
            float wtn0 = wt_s[256 + j0],  wtn1 = wt_s[256 + j0 + 1];
            #pragma unroll
            for (int mi = 0; mi < 4; mi++) {
                int r0 = (mh * 4 + mi) * 16 + g, r1 = r0 + 8;
                float tv0 = t_s[r0], tv1 = t_s[r1];
                float2 hv0 = *(const float2*)(Hg + r0 * 128 + j0);
                float2 hv1 = *(const float2*)(Hg + r1 * 128 + j0);
                {
                    float r = sigmoid_f(aR[mi][0] + brzr0 + tv0 * wtr0);
                    float z = sigmoid_f(aZ[mi][0] + brzz0 + tv0 * wtz0);
                    float n = tanhf(aNi[mi][0] + tv0 * wtn0 + bni0 + r * (aNh[mi][0] + bnh0));
                    nh_s[r0 * NHP + j0] = (1.f - z) * n + z * hv0.x;
                }
                {
                    float r = sigmoid_f(aR[mi][1] + brzr1 + tv0 * wtr1);
                    float z = sigmoid_f(aZ[mi][1] + brzz1 + tv0 * wtz1);
                    float n = tanhf(aNi[mi][1] + tv0 * wtn1 + bni1 + r * (aNh[mi][1] + bnh1));
                    nh_s[r0 * NHP + j0 + 1] = (1.f - z) * n + z * hv0.y;
                }
                {
                    float r = sigmoid_f(aR[mi][2] + brzr0 + tv1 * wtr0);
                    float z = sigmoid_f(aZ[mi][2] + brzz0 + tv1 * wtz0);
                    float n = tanhf(aNi[mi][2] + tv1 * wtn0 + bni0 + r * (aNh[mi][2] + bnh0));
                    nh_s[r1 * NHP + j0] = (1.f - z) * n + z * hv1.x;
                }
                {
                    float r = sigmoid_f(aR[mi][3] + brzr1 + tv1 * wtr1);
                    float z = sigmoid_f(aZ[mi][3] + brzz1 + tv1 * wtz1);
                    float n = tanhf(aNi[mi][3] + tv1 * wtn1 + bni1 + r * (aNh[mi][3] + bnh1));
                    nh_s[r1 * NHP + j0 + 1] = (1.f - z) * n + z * hv1.y;
                }
            }
        }
    }
    __syncthreads();

    // ---- store new_h (pre-sync) coalesced; block partials ----
    float* NH = dout + 65 + (size_t)blk * MT * 128;
    #pragma unroll
    for (int i = tid; i < MT * 128; i += TPB) {
        int c = i >> 7, k = i & 127;
        NH[i] = nh_s[c * NHP + k];
    }
    if (tid < 128) {
        float s = 0.f;
        #pragma unroll 8
        for (int c = 0; c < MT; c++) s += nh_s[c * NHP + tid];
        g_blk_h[(size_t)blk * 128 + tid] = s;
    }
    if (tid < 64) {
        float s = 0.f;
        #pragma unroll 8
        for (int c = 0; c < MT; c++) s += e_s[c] * __half2float(outh[c * OHP + tid]);
        g_blk_wout[(size_t)blk * 64 + tid] = s;
    } else if (tid == 64) {
        float s = 0.f;
        for (int c = 0; c < MT; c++) s += t_s[c];
        g_blk_t[blk] = s;
    } else if (tid == 96) {
        float s = 0.f;
        for (int c = 0; c < MT; c++) s += e_s[c];
        g_blk_e[blk] = s;
    }
}

// ---------------- Kernel C: global reductions + head ----------------
__global__ __launch_bounds__(1024) void kC(
    const float* __restrict__ Wo, const float* __restrict__ bo,
    float* __restrict__ dout)
{
    __shared__ float s_red[1024];
    __shared__ float s_red2[1024];
    __shared__ float s_comb[64];
    __shared__ float s_esum;
    const int tid = threadIdx.x;

    // faction sums: thread = (faction f, hidden j); 128 blocks per faction
    {
        int f = tid >> 7, j = tid & 127;
        const float* p = g_blk_h + (size_t)(f * 128) * 128 + j;
        float s = 0.f;
        #pragma unroll 8
        for (int b = 0; b < 128; b++) s += p[b * 128];
        g_fm[f * 128 + j] = s * (1.f / 16384.f);
        s_red[tid] = s;
    }
    __syncthreads();
    if (tid < 128) {
        float gg = 0.f;
        #pragma unroll
        for (int f = 0; f < 8; f++) gg += s_red[f * 128 + tid];
        g_go[tid] = gg * (1.f / (float)NCELLS);
    }
    __syncthreads();

    // weighted-out numerator: 16 chunks x 64 outputs, 64 blocks/chunk
    {
        int o = tid & 63, ch = tid >> 6;
        const float* p = g_blk_wout + (size_t)(ch * 64) * 64 + o;
        float s = 0.f;
        #pragma unroll 8
        for (int b = 0; b < 64; b++) s += p[b * 64];
        s_red[tid] = s;
    }
    __syncthreads();
    if (tid < 64) {
        float s = 0.f;
        #pragma unroll
        for (int ch = 0; ch < 16; ch++) s += s_red[ch * 64 + tid];
        s_comb[tid] = s;
    }
    __syncthreads();

    // exp-sum + t-sum (one element per thread, NBLK==1024)
    s_red[tid]  = g_blk_e[tid];
    s_red2[tid] = g_blk_t[tid];
    __syncthreads();
    for (int off = 512; off > 0; off >>= 1) {
        if (tid < off) { s_red[tid] += s_red[tid + off]; s_red2[tid] += s_red2[tid + off]; }
        __syncthreads();
    }
    if (tid == 0) {
        s_esum = s_red[0];
        dout[64] = s_red2[0] * (1.f / (float)NCELLS);
    }
    __syncthreads();

    if (tid < 64) s_comb[tid] *= (1.f / s_esum);
    __syncthreads();
    if (tid < 64) {
        float p = bo[tid];
        const float* wr = Wo + tid * 64;
        #pragma unroll 8
        for (int o = 0; o < 64; o++) p += wr[o] * s_comb[o];
        dout[tid] = p;
    }
}

// ---------------- Kernel D: faction sync (in-place on d_out new_h) ----------------
__global__ __launch_bounds__(512) void kD(float* __restrict__ nh, const void* __restrict__ stepPtr)
{
    int iv = *(const int*)stepPtr;
    int step = (iv >= 0 && iv < 1000000) ? iv : (int)(*(const float*)stepPtr);
    const bool debate = (step > 5);

    unsigned base = blockIdx.x * 512u + threadIdx.x;
    const unsigned stride = 2048u * 512u;
    #pragma unroll 4
    for (int r = 0; r < 16; r++) {
        unsigned e = base + (unsigned)r * stride;
        unsigned cell = e >> 7;
        unsigned j = e & 127u;
        unsigned f = cell >> 14;
        unsigned pos = cell & 16383u;
        float v = nh[e];
        v = 0.85f * v + 0.15f * g_fm[f * 128 + j];
        if (debate && pos < 4096u) v = 0.85f * v + 0.15f * g_go[j];
        nh[e] = v;
    }
}

// ---------------- launcher ----------------
extern "C" void kernel_launch(void* const* d_in, const int* in_sizes, int n_in,
                              void* d_out, int out_size)
{
    const float* x    = (const float*)d_in[0];
    const float* hid  = (const float*)d_in[1];
    const float* W1a  = (const float*)d_in[2];
    const float* b1a  = (const float*)d_in[3];
    const float* W2a  = (const float*)d_in[4];
    const float* b2a  = (const float*)d_in[5];
    const float* W1g  = (const float*)d_in[6];
    const float* b1g  = (const float*)d_in[7];
    const float* W2g  = (const float*)d_in[8];
    const float* b2g  = (const float*)d_in[9];
    const float* Wih  = (const float*)d_in[10];
    const float* Whh  = (const float*)d_in[11];
    const float* bih  = (const float*)d_in[12];
    const float* bhh  = (const float*)d_in[13];
    const float* Wo   = (const float*)d_in[14];
    const float* bo   = (const float*)d_in[15];
    const void*  step = (n_in > 16) ? (const void*)d_in[16] : (const void*)d_in[15];

    float* out = (float*)d_out;
    float* nh  = out + 65;

    cudaFuncSetAttribute(kB, cudaFuncAttributeMaxDynamicSharedMemorySize, SMEM_KB_BYTES);

    kA1<<<24, 512>>>(W1a, W1g, W2a, W2g);
    kA2<<<36, 512>>>(Wih, Whh);
    kA3<<<3, 512>>>(x, W1a, b1a, W1g, b1g, b2a, b2g, Wih, bih, bhh);
    kB<<<NBLK, TPB, SMEM_KB_BYTES>>>(hid, out);
    kC<<<1, 1024>>>(Wo, bo, out);
    kD<<<2048, 512>>>(nh, step);
}

// round 10
// speedup vs baseline: 7.4531x; 1.0883x over previous
#include <cuda_runtime.h>
#include <cuda_fp16.h>
#include <stdint.h>
#include <math.h>

// ---------------- problem constants ----------------
#define NCELLS 131072
#define MT   128
#define TPB  512
#define NBLK (NCELLS / MT)   // 1024

// ---------------- smem layout (float offsets) ----------------
// all half pitches are ≡ 16 (mod 128) BYTES -> ldmatrix 8-row groups conflict-free
#define HHP   136            // h_h half pitch   (272 B)
#define C1HP  264            // C1h half pitch   (528 B)
#define OHP   72             // out_h half pitch (144 B)
#define NHP   132            // nh fp32 pitch (aliases C1 region)

#define OFF_HH   0                        // 128*136 h = 8704 floats
#define OFF_C1H  8704                     // 128*264 h = 16896 floats (aliased by nh fp32 128*132)
#define OFF_OUTH 25600                    // 128*72 h  = 4608 floats
#define OFF_T    30208                    // 128
#define OFF_E    30336                    // 128
#define OFF_XC   30464                    // 256
#define OFF_B2D  30720                    // 64
#define OFF_BRZ  30784                    // 256
#define OFF_BNI  31040                    // 128
#define OFF_BNH  31168                    // 128
#define OFF_WT   31296                    // 384
#define SMEM_KB_FLOATS 31680
#define SMEM_KB_BYTES  (SMEM_KB_FLOATS * 4)   // 126720 B

// ---------------- device scratch (static, allocation-free) ----------------
__device__ uint2 g_B1h[8 * 32 * 32];     // stage1  K=128,N=256
__device__ uint2 g_B2h[16 * 8 * 32];     // stage2  K=256,N=64 (sign-folded)
__device__ uint2 g_B3h[8 * 48 * 32];     // GRU Whh K=128,N=384
__device__ uint2 g_B4h[4 * 48 * 32];     // GRU Wih K=64, N=384
__device__ float g_xc[256];
__device__ float g_b2d[64];
__device__ float g_brz[256];
__device__ float g_bni[128];
__device__ float g_bnh[128];
__device__ float g_wt[384];
__device__ float g_blk_t[NBLK];
__device__ float g_blk_e[NBLK];
__device__ float g_blk_wout[NBLK * 64];
__device__ float g_blk_h[NBLK * 128];
__device__ float g_fm[8 * 128];
__device__ float g_go[128];

// ---------------- helpers ----------------
__device__ __forceinline__ unsigned packh2(float lo, float hi) {
    __half2 h = __floats2half2_rn(lo, hi);
    return *(unsigned*)&h;
}
__device__ __forceinline__ void mma16(float* c,
    unsigned a0, unsigned a1, unsigned a2, unsigned a3,
    unsigned b0, unsigned b1)
{
    asm volatile(
        "mma.sync.aligned.m16n8k16.row.col.f32.f16.f16.f32 "
        "{%0,%1,%2,%3},{%4,%5,%6,%7},{%8,%9},{%0,%1,%2,%3};"
        : "+f"(c[0]), "+f"(c[1]), "+f"(c[2]), "+f"(c[3])
        : "r"(a0), "r"(a1), "r"(a2), "r"(a3), "r"(b0), "r"(b1));
}
__device__ __forceinline__ void ldsm4(unsigned& a0, unsigned& a1, unsigned& a2, unsigned& a3,
                                      unsigned addr)
{
    asm volatile("ldmatrix.sync.aligned.m8n8.x4.shared.b16 {%0,%1,%2,%3}, [%4];"
                 : "=r"(a0), "=r"(a1), "=r"(a2), "=r"(a3) : "r"(addr));
}
__device__ __forceinline__ float sigmoid_f(float x) {
    return 1.f / (1.f + __expf(-x));
}

// ---------------- kA1: pack B1h + B2h ----------------
__global__ __launch_bounds__(512) void kA1(
    const float* __restrict__ W1a, const float* __restrict__ W1g,
    const float* __restrict__ W2a, const float* __restrict__ W2g)
{
    int id = blockIdx.x * 512 + threadIdx.x;
    if (id < 8192) {                                  // B1h: B[k][u]=W1[u][64+k]
        int grp = id >> 10, rem = id & 1023;
        int nt = rem >> 5, lane = rem & 31;
        int t = lane & 3, g = lane >> 2;
        int u = nt * 8 + g;
        const float* wr = ((u < 128) ? (W1a + u * 192) : (W1g + (u - 128) * 192)) + 64 + grp * 16;
        g_B1h[id] = make_uint2(packh2(wr[2*t], wr[2*t+1]), packh2(wr[2*t+8], wr[2*t+9]));
    } else if (id < 12288) {                          // B2h: +W2a / -W2g
        int i = id - 8192;
        int grpG = i >> 8, rem = i & 255;
        int nt = rem >> 5, lane = rem & 31;
        int t = lane & 3, g = lane >> 2;
        int o = nt * 8 + g;
        if (grpG < 8) {
            const float* wr = W2a + o * 128 + grpG * 16;
            g_B2h[i] = make_uint2(packh2(wr[2*t], wr[2*t+1]), packh2(wr[2*t+8], wr[2*t+9]));
        } else {
            const float* wr = W2g + o * 128 + (grpG - 8) * 16;
            g_B2h[i] = make_uint2(packh2(-wr[2*t], -wr[2*t+1]), packh2(-wr[2*t+8], -wr[2*t+9]));
        }
    }
}

// ---------------- kA2: pack B3h + B4h ----------------
__global__ __launch_bounds__(512) void kA2(
    const float* __restrict__ Wih, const float* __restrict__ Whh)
{
    int id = blockIdx.x * 512 + threadIdx.x;
    if (id < 12288) {                                 // B3h: Whh[j][k]
        int grp = id / 1536, rem = id % 1536;
        int nt = rem >> 5, lane = rem & 31;
        int t = lane & 3, g = lane >> 2;
        int j = nt * 8 + g;
        const float* wr = Whh + j * 128 + grp * 16;
        g_B3h[id] = make_uint2(packh2(wr[2*t], wr[2*t+1]), packh2(wr[2*t+8], wr[2*t+9]));
    } else if (id < 18432) {                          // B4h: Wih[j][k], k<64
        int i = id - 12288;
        int grp = i / 1536, rem = i % 1536;
        int nt = rem >> 5, lane = rem & 31;
        int t = lane & 3, g = lane >> 2;
        int j = nt * 8 + g;
        const float* wr = Wih + j * 65 + grp * 16;
        g_B4h[i] = make_uint2(packh2(wr[2*t], wr[2*t+1]), packh2(wr[2*t+8], wr[2*t+9]));
    }
}

// ---------------- kA3: misc vectors ----------------
__global__ __launch_bounds__(512) void kA3(
    const float* __restrict__ x,
    const float* __restrict__ W1a, const float* __restrict__ b1a,
    const float* __restrict__ W1g, const float* __restrict__ b1g,
    const float* __restrict__ b2a, const float* __restrict__ b2g,
    const float* __restrict__ Wih,
    const float* __restrict__ bih, const float* __restrict__ bhh)
{
    int id = blockIdx.x * 512 + threadIdx.x;
    if (id < 256) {                                   // xc (exact fp32 x-fold)
        const float* W = (id < 128) ? W1a : W1g;
        const float* b = (id < 128) ? b1a : b1g;
        int j = id & 127;
        float s = b[j];
        const float* row = W + j * 192;
        #pragma unroll 8
        for (int k = 0; k < 64; k++) s += row[k] * x[k];
        g_xc[id] = s;
    } else if (id < 320) {
        int o = id - 256;
        g_b2d[o] = b2a[o] - b2g[o];
    } else if (id < 704) {
        int j = id - 320;
        g_wt[j] = Wih[j * 65 + 64];
    } else if (id < 960) {
        int j = id - 704;
        g_brz[j] = bih[j] + bhh[j];
    } else if (id < 1088) {
        int j = id - 960;
        g_bni[j] = bih[256 + j];
    } else if (id < 1216) {
        int j = id - 1088;
        g_bnh[j] = bhh[256 + j];
    }
}

// ---------------- Kernel B: fused per-cell pipeline (fp16 MMA + ldmatrix) ----------------
__global__ __launch_bounds__(512, 1) void kB(
    const float* __restrict__ hiddens,
    float* __restrict__ dout)
{
    extern __shared__ float sm[];
    __half* h_h   = (__half*)(sm + OFF_HH);
    __half* c1h   = (__half*)(sm + OFF_C1H);
    float*  nh_s  = sm + OFF_C1H;        // aliases c1h after stage 2
    __half* outh  = (__half*)(sm + OFF_OUTH);
    float*  t_s   = sm + OFF_T;
    float*  e_s   = sm + OFF_E;
    float*  xc_s  = sm + OFF_XC;
    float*  b2d_s = sm + OFF_B2D;
    float*  brz_s = sm + OFF_BRZ;
    float*  bni_s = sm + OFF_BNI;
    float*  bnh_s = sm + OFF_BNH;
    float*  wt_s  = sm + OFF_WT;

    const int tid  = threadIdx.x;
    const int blk  = blockIdx.x;
    const int w    = tid >> 5;
    const int lane = tid & 31;
    const int t4   = lane & 3;
    const int g    = lane >> 2;

    // ldmatrix per-lane byte offsets (row = lane&15, col-half = lane>>4)
    const unsigned sb   = (unsigned)__cvta_generic_to_shared(sm);
    const int lrow = lane & 15, lcol = lane >> 4;
    const unsigned hB   = sb + OFF_HH  * 4 + 2u * (lrow * HHP  + lcol * 8);
    const unsigned c1B  = sb + OFF_C1H * 4 + 2u * (lrow * C1HP + lcol * 8);
    const unsigned oB   = sb + OFF_OUTH* 4 + 2u * (lrow * OHP  + lcol * 8);

    const float* Hg = hiddens + (size_t)blk * MT * 128;

    // ---- stage 0: load h tile (fp16) + constant tables ----
    #pragma unroll
    for (int i = tid; i < MT * 32; i += TPB) {       // 4096 float4
        float4 v = ((const float4*)Hg)[i];
        int c = i >> 5, k = (i & 31) << 2;
        unsigned* q = (unsigned*)(h_h + c * HHP + k);
        q[0] = packh2(v.x, v.y);
        q[1] = packh2(v.z, v.w);
    }
    if (tid < 256) { xc_s[tid] = g_xc[tid]; brz_s[tid] = g_brz[tid]; }
    if (tid < 64)  { b2d_s[tid] = g_b2d[tid]; }
    if (tid < 128) { bni_s[tid] = g_bni[tid]; bnh_s[tid] = g_bnh[tid]; }
    if (tid < 384) { wt_s[tid] = g_wt[tid]; }
    __syncthreads();

    // ---- stage 1: C1[128x256] = relu(h @ B1 + xc); warp owns 16 cols, loops 8 m-tiles ----
    {
        float acc[8][2][4];
        #pragma unroll
        for (int m = 0; m < 8; m++)
            #pragma unroll
            for (int n = 0; n < 2; n++)
                #pragma unroll
                for (int c = 0; c < 4; c++) acc[m][n][c] = 0.f;
        #pragma unroll
        for (int grp = 0; grp < 8; grp++) {
            uint2 bv0 = g_B1h[(grp * 32 + 2 * w)     * 32 + lane];
            uint2 bv1 = g_B1h[(grp * 32 + 2 * w + 1) * 32 + lane];
            #pragma unroll
            for (int m = 0; m < 8; m++) {
                unsigned a0, a1, a2, a3;
                ldsm4(a0, a1, a2, a3, hB + 2u * (m * 16 * HHP + grp * 16));
                mma16(acc[m][0], a0, a1, a2, a3, bv0.x, bv0.y);
                mma16(acc[m][1], a0, a1, a2, a3, bv1.x, bv1.y);
            }
        }
        #pragma unroll
        for (int m = 0; m < 8; m++) {
            int r0 = m * 16 + g, r1 = r0 + 8;
            #pragma unroll
            for (int n = 0; n < 2; n++) {
                int cb = w * 16 + n * 8 + 2 * t4;
                float x0 = xc_s[cb], x1 = xc_s[cb + 1];
                *(unsigned*)(c1h + r0 * C1HP + cb) =
                    packh2(fmaxf(acc[m][n][0] + x0, 0.f), fmaxf(acc[m][n][1] + x1, 0.f));
                *(unsigned*)(c1h + r1 * C1HP + cb) =
                    packh2(fmaxf(acc[m][n][2] + x0, 0.f), fmaxf(acc[m][n][3] + x1, 0.f));
            }
        }
    }
    __syncthreads();

    // ---- stage 2: out[128x64] = C1 @ B2 + b2d; warp = (m-tile w&7, n-half w>>3), full K ----
    {
        const int mt = w & 7, nh4 = w >> 3;
        float acc[4][4];
        #pragma unroll
        for (int n = 0; n < 4; n++)
            #pragma unroll
            for (int c = 0; c < 4; c++) acc[n][c] = 0.f;
        #pragma unroll
        for (int grpG = 0; grpG < 16; grpG++) {
            unsigned a0, a1, a2, a3;
            ldsm4(a0, a1, a2, a3, c1B + 2u * (mt * 16 * C1HP + grpG * 16));
            #pragma unroll
            for (int ni = 0; ni < 4; ni++) {
                uint2 bv = g_B2h[(grpG * 8 + nh4 * 4 + ni) * 32 + lane];
                mma16(acc[ni], a0, a1, a2, a3, bv.x, bv.y);
            }
        }
        int r0 = mt * 16 + g, r1 = r0 + 8;
        #pragma unroll
        for (int ni = 0; ni < 4; ni++) {
            int o = (nh4 * 4 + ni) * 8 + 2 * t4;
            float x0 = b2d_s[o], x1 = b2d_s[o + 1];
            *(unsigned*)(outh + r0 * OHP + o) = packh2(acc[ni][0] + x0, acc[ni][1] + x1);
            *(unsigned*)(outh + r1 * OHP + o) = packh2(acc[ni][2] + x0, acc[ni][3] + x1);
        }
    }
    __syncthreads();

    // ---- t/e (tid<128) — overlapped with GRU pass-1 mma of all warps ----
    if (tid < 128) {
        const unsigned* orow = (const unsigned*)(outh + tid * OHP);
        float s = 0.f;
        #pragma unroll
        for (int c = 0; c < 32; c++) {
            float2 f = __half22float2(*(const __half2*)(orow + c));
            s += f.x * f.x + f.y * f.y;
        }
        float tt = s * (1.f / 64.f);
        t_s[tid] = tt;
        e_s[tid] = expf(tt);
    }

    // ---- GRU: warp owns j-slice [w*8,(w+1)*8), two m-half passes ----
    #pragma unroll 1
    for (int mh = 0; mh < 2; mh++) {
        float aR[4][4], aZ[4][4], aNh[4][4], aNi[4][4];
        #pragma unroll
        for (int m = 0; m < 4; m++)
            #pragma unroll
            for (int c = 0; c < 4; c++)
                { aR[m][c] = 0.f; aZ[m][c] = 0.f; aNh[m][c] = 0.f; aNi[m][c] = 0.f; }

        // h-side (K=128)
        #pragma unroll
        for (int grp = 0; grp < 8; grp++) {
            uint2 bR = g_B3h[(grp * 48 + w)      * 32 + lane];
            uint2 bZ = g_B3h[(grp * 48 + 16 + w) * 32 + lane];
            uint2 bN = g_B3h[(grp * 48 + 32 + w) * 32 + lane];
            #pragma unroll
            for (int mi = 0; mi < 4; mi++) {
                unsigned a0, a1, a2, a3;
                ldsm4(a0, a1, a2, a3, hB + 2u * ((mh * 4 + mi) * 16 * HHP + grp * 16));
                mma16(aR[mi],  a0, a1, a2, a3, bR.x, bR.y);
                mma16(aZ[mi],  a0, a1, a2, a3, bZ.x, bZ.y);
                mma16(aNh[mi], a0, a1, a2, a3, bN.x, bN.y);
            }
        }
        // i-side (K=64)
        #pragma unroll
        for (int grp = 0; grp < 4; grp++) {
            uint2 bR = g_B4h[(grp * 48 + w)      * 32 + lane];
            uint2 bZ = g_B4h[(grp * 48 + 16 + w) * 32 + lane];
            uint2 bN = g_B4h[(grp * 48 + 32 + w) * 32 + lane];
            #pragma unroll
            for (int mi = 0; mi < 4; mi++) {
                unsigned a0, a1, a2, a3;
                ldsm4(a0, a1, a2, a3, oB + 2u * ((mh * 4 + mi) * 16 * OHP + grp * 16));
                mma16(aR[mi],  a0, a1, a2, a3, bR.x, bR.y);
                mma16(aZ[mi],  a0, a1, a2, a3, bZ.x, bZ.y);
                mma16(aNi[mi], a0, a1, a2, a3, bN.x, bN.y);
            }
        }

        if (mh == 0) __syncthreads();   // t_s/e_s ready; stage-2 c1h reads complete -> nh alias safe

        // epilogue: nh into staging (c1h alias); exact fp32 h re-read from global (L2-hot)
        {
            int j0 = w * 8 + 2 * t4;
            float brzr0 = brz_s[j0],       brzr1 = brz_s[j0 + 1];
            float brzz0 = brz_s[128 + j0], brzz1 = brz_s[128 + j0 + 1];
            float bni0  = bni_s[j0],       bni1  = bni_s[j0 + 1];
            float bnh0  = bnh_s[j0],       bnh1  = bnh_s[j0 + 1];
            float wtr0 = wt_s[j0],        wtr1 = wt_s[j0 + 1];
            float wtz0 = wt_s[128 + j0],  wtz1 = wt_s[128 + j0 + 1];
            float wtn0 = wt_s[256 + j0],  wtn1 = wt_s[256 + j0 + 1];
            #pragma unroll
            for (int mi = 0; mi < 4; mi++) {
                int r0 = (mh * 4 + mi) * 16 + g, r1 = r0 + 8;
                float tv0 = t_s[r0], tv1 = t_s[r1];
                float2 hv0 = *(const float2*)(Hg + r0 * 128 + j0);
                float2 hv1 = *(const float2*)(Hg + r1 * 128 + j0);
                {
                    float r = sigmoid_f(aR[mi][0] + brzr0 + tv0 * wtr0);
                    float z = sigmoid_f(aZ[mi][0] + brzz0 + tv0 * wtz0);
                    float n = tanhf(aNi[mi][0] + tv0 * wtn0 + bni0 + r * (aNh[mi][0] + bnh0));
                    nh_s[r0 * NHP + j0] = (1.f - z) * n + z * hv0.x;
                }
                {
                    float r = sigmoid_f(aR[mi][1] + brzr1 + tv0 * wtr1);
                    float z = sigmoid_f(aZ[mi][1] + brzz1 + tv0 * wtz1);
                    float n = tanhf(aNi[mi][1] + tv0 * wtn1 + bni1 + r * (aNh[mi][1] + bnh1));
                    nh_s[r0 * NHP + j0 + 1] = (1.f - z) * n + z * hv0.y;
                }
                {
                    float r = sigmoid_f(aR[mi][2] + brzr0 + tv1 * wtr0);
                    float z = sigmoid_f(aZ[mi][2] + brzz0 + tv1 * wtz0);
                    float n = tanhf(aNi[mi][2] + tv1 * wtn0 + bni0 + r * (aNh[mi][2] + bnh0));
                    nh_s[r1 * NHP + j0] = (1.f - z) * n + z * hv1.x;
                }
                {
                    float r = sigmoid_f(aR[mi][3] + brzr1 + tv1 * wtr1);
                    float z = sigmoid_f(aZ[mi][3] + brzz1 + tv1 * wtz1);
                    float n = tanhf(aNi[mi][3] + tv1 * wtn1 + bni1 + r * (aNh[mi][3] + bnh1));
                    nh_s[r1 * NHP + j0 + 1] = (1.f - z) * n + z * hv1.y;
                }
            }
        }
    }
    __syncthreads();

    // ---- store new_h (pre-sync) coalesced; block partials ----
    float* NH = dout + 65 + (size_t)blk * MT * 128;
    #pragma unroll
    for (int i = tid; i < MT * 128; i += TPB) {
        int c = i >> 7, k = i & 127;
        NH[i] = nh_s[c * NHP + k];
    }
    if (tid < 128) {
        float s = 0.f;
        #pragma unroll 8
        for (int c = 0; c < MT; c++) s += nh_s[c * NHP + tid];
        g_blk_h[(size_t)blk * 128 + tid] = s;
    }
    if (tid < 64) {
        float s = 0.f;
        #pragma unroll 8
        for (int c = 0; c < MT; c++) s += e_s[c] * __half2float(outh[c * OHP + tid]);
        g_blk_wout[(size_t)blk * 64 + tid] = s;
    } else if (tid == 64) {
        float s = 0.f;
        for (int c = 0; c < MT; c++) s += t_s[c];
        g_blk_t[blk] = s;
    } else if (tid == 96) {
        float s = 0.f;
        for (int c = 0; c < MT; c++) s += e_s[c];
        g_blk_e[blk] = s;
    }
}

// ---------------- Kernel C: global reductions + head ----------------
__global__ __launch_bounds__(1024) void kC(
    const float* __restrict__ Wo, const float* __restrict__ bo,
    float* __restrict__ dout)
{
    __shared__ float s_red[1024];
    __shared__ float s_red2[1024];
    __shared__ float s_comb[64];
    __shared__ float s_esum;
    const int tid = threadIdx.x;

    {
        int f = tid >> 7, j = tid & 127;
        const float* p = g_blk_h + (size_t)(f * 128) * 128 + j;
        float s = 0.f;
        #pragma unroll 8
        for (int b = 0; b < 128; b++) s += p[b * 128];
        g_fm[f * 128 + j] = s * (1.f / 16384.f);
        s_red[tid] = s;
    }
    __syncthreads();
    if (tid < 128) {
        float gg = 0.f;
        #pragma unroll
        for (int f = 0; f < 8; f++) gg += s_red[f * 128 + tid];
        g_go[tid] = gg * (1.f / (float)NCELLS);
    }
    __syncthreads();

    {
        int o = tid & 63, ch = tid >> 6;
        const float* p = g_blk_wout + (size_t)(ch * 64) * 64 + o;
        float s = 0.f;
        #pragma unroll 8
        for (int b = 0; b < 64; b++) s += p[b * 64];
        s_red[tid] = s;
    }
    __syncthreads();
    if (tid < 64) {
        float s = 0.f;
        #pragma unroll
        for (int ch = 0; ch < 16; ch++) s += s_red[ch * 64 + tid];
        s_comb[tid] = s;
    }
    __syncthreads();

    s_red[tid]  = g_blk_e[tid];
    s_red2[tid] = g_blk_t[tid];
    __syncthreads();
    for (int off = 512; off > 0; off >>= 1) {
        if (tid < off) { s_red[tid] += s_red[tid + off]; s_red2[tid] += s_red2[tid + off]; }
        __syncthreads();
    }
    if (tid == 0) {
        s_esum = s_red[0];
        dout[64] = s_red2[0] * (1.f / (float)NCELLS);
    }
    __syncthreads();

    if (tid < 64) s_comb[tid] *= (1.f / s_esum);
    __syncthreads();
    if (tid < 64) {
        float p = bo[tid];
        const float* wr = Wo + tid * 64;
        #pragma unroll 8
        for (int o = 0; o < 64; o++) p += wr[o] * s_comb[o];
        dout[tid] = p;
    }
}

// ---------------- Kernel D: faction sync, float4 RMW with scalar peel ----------------
// nh = dout+65; nh+3 is 16B-aligned. Chunks cover e in [3, 16777215); peel e=0,1,2 and e=16777215.
__global__ __launch_bounds__(512) void kD(float* __restrict__ nh, const void* __restrict__ stepPtr)
{
    int iv = *(const int*)stepPtr;
    int step = (iv >= 0 && iv < 1000000) ? iv : (int)(*(const float*)stepPtr);
    const bool debate = (step > 5);

    if (blockIdx.x == 0 && threadIdx.x < 4) {
        unsigned e = (threadIdx.x < 3) ? threadIdx.x : 16777215u;
        unsigned cell = e >> 7, j = e & 127u;
        unsigned f = cell >> 14, pos = cell & 16383u;
        float v = nh[e];
        v = 0.85f * v + 0.15f * g_fm[f * 128 + j];
        if (debate && pos < 4096u) v = 0.85f * v + 0.15f * g_go[j];
        nh[e] = v;
    }

    float4* nh4 = (float4*)(nh + 3);
    unsigned base = blockIdx.x * 512u + threadIdx.x;
    const unsigned stride = 2048u * 512u;
    #pragma unroll
    for (int r = 0; r < 4; r++) {
        unsigned q = base + (unsigned)r * stride;
        if (q < 4194303u) {
            float4 v = nh4[q];
            float va[4] = {v.x, v.y, v.z, v.w};
            unsigned e0 = 3u + 4u * q;
            #pragma unroll
            for (int i = 0; i < 4; i++) {
                unsigned e = e0 + (unsigned)i;
                unsigned cell = e >> 7, j = e & 127u;
                unsigned f = cell >> 14, pos = cell & 16383u;
                float val = va[i];
                val = 0.85f * val + 0.15f * g_fm[f * 128 + j];
                if (debate && pos < 4096u) val = 0.85f * val + 0.15f * g_go[j];
                va[i] = val;
            }
            nh4[q] = make_float4(va[0], va[1], va[2], va[3]);
        }
    }
}

// ---------------- launcher ----------------
extern "C" void kernel_launch(void* const* d_in, const int* in_sizes, int n_in,
                              void* d_out, int out_size)
{
    const float* x    = (const float*)d_in[0];
    const float* hid  = (const float*)d_in[1];
    const float* W1a  = (const float*)d_in[2];
    const float* b1a  = (const float*)d_in[3];
    const float* W2a  = (const float*)d_in[4];
    const float* b2a  = (const float*)d_in[5];
    const float* W1g  = (const float*)d_in[6];
    const float* b1g  = (const float*)d_in[7];
    const float* W2g  = (const float*)d_in[8];
    const float* b2g  = (const float*)d_in[9];
    const float* Wih  = (const float*)d_in[10];
    const float* Whh  = (const float*)d_in[11];
    const float* bih  = (const float*)d_in[12];
    const float* bhh  = (const float*)d_in[13];
    const float* Wo   = (const float*)d_in[14];
    const float* bo   = (const float*)d_in[15];
    const void*  step = (n_in > 16) ? (const void*)d_in[16] : (const void*)d_in[15];

    float* out = (float*)d_out;
    float* nh  = out + 65;

    cudaFuncSetAttribute(kB, cudaFuncAttributeMaxDynamicSharedMemorySize, SMEM_KB_BYTES);

    kA1<<<24, 512>>>(W1a, W1g, W2a, W2g);
    kA2<<<36, 512>>>(Wih, Whh);
    kA3<<<3, 512>>>(x, W1a, b1a, W1g, b1g, b2a, b2g, Wih, bih, bhh);
    kB<<<NBLK, TPB, SMEM_KB_BYTES>>>(hid, out);
    kC<<<1, 1024>>>(Wo, bo, out);
    kD<<<2048, 512>>>(nh, step);
}

// round 11
// speedup vs baseline: 7.8293x; 1.0505x over previous
#include <cuda_runtime.h>
#include <cuda_fp16.h>
#include <stdint.h>
#include <math.h>

// ---------------- problem constants ----------------
#define NCELLS 131072
#define MT   64
#define TPB  256
#define NBLK (NCELLS / MT)   // 2048

// ---------------- smem layout (float offsets) ----------------
// all half pitches are ≡ 16 (mod 128) BYTES -> ldmatrix 8-row groups conflict-free
#define HHP   136            // h_h half pitch   (272 B)
#define C1HP  264            // C1h half pitch   (528 B)
#define OHP   72             // out_h half pitch (144 B)
#define NHP   132            // nh fp32 pitch (aliases C1 region exactly: 64*132 = 64*264/2)

#define OFF_HH   0                        // 64*136 h = 4352 floats
#define OFF_C1H  4352                     // 64*264 h = 8448 floats (nh fp32 alias 64*132)
#define OFF_OUTH 12800                    // 64*72 h  = 2304 floats
#define OFF_T    15104                    // 64
#define OFF_E    15168                    // 64
#define OFF_XC   15232                    // 256
#define OFF_B2D  15488                    // 64
#define OFF_BRZ  15552                    // 256
#define OFF_BNI  15808                    // 128
#define OFF_BNH  15936                    // 128
#define OFF_WT   16064                    // 384
#define SMEM_KB_FLOATS 16448
#define SMEM_KB_BYTES  (SMEM_KB_FLOATS * 4)   // 65792 B -> 2 blocks/SM

// ---------------- device scratch (static, allocation-free) ----------------
__device__ uint2 g_B1h[8 * 32 * 32];     // stage1  K=128,N=256
__device__ uint2 g_B2h[16 * 8 * 32];     // stage2  K=256,N=64 (sign-folded)
__device__ uint2 g_B3h[8 * 48 * 32];     // GRU Whh K=128,N=384
__device__ uint2 g_B4h[4 * 48 * 32];     // GRU Wih K=64, N=384
__device__ float g_xc[256];
__device__ float g_b2d[64];
__device__ float g_brz[256];
__device__ float g_bni[128];
__device__ float g_bnh[128];
__device__ float g_wt[384];
__device__ float g_blk_t[NBLK];
__device__ float g_blk_e[NBLK];
__device__ float g_blk_wout[NBLK * 64];
__device__ float g_blk_h[NBLK * 128];
__device__ float g_fm[8 * 128];
__device__ float g_go[128];

// ---------------- helpers ----------------
__device__ __forceinline__ unsigned packh2(float lo, float hi) {
    __half2 h = __floats2half2_rn(lo, hi);
    return *(unsigned*)&h;
}
__device__ __forceinline__ void mma16(float* c,
    unsigned a0, unsigned a1, unsigned a2, unsigned a3,
    unsigned b0, unsigned b1)
{
    asm volatile(
        "mma.sync.aligned.m16n8k16.row.col.f32.f16.f16.f32 "
        "{%0,%1,%2,%3},{%4,%5,%6,%7},{%8,%9},{%0,%1,%2,%3};"
        : "+f"(c[0]), "+f"(c[1]), "+f"(c[2]), "+f"(c[3])
        : "r"(a0), "r"(a1), "r"(a2), "r"(a3), "r"(b0), "r"(b1));
}
__device__ __forceinline__ void ldsm4(unsigned& a0, unsigned& a1, unsigned& a2, unsigned& a3,
                                      unsigned addr)
{
    asm volatile("ldmatrix.sync.aligned.m8n8.x4.shared.b16 {%0,%1,%2,%3}, [%4];"
                 : "=r"(a0), "=r"(a1), "=r"(a2), "=r"(a3) : "r"(addr));
}
__device__ __forceinline__ float sigmoid_f(float x) {
    return 1.f / (1.f + __expf(-x));
}

// ---------------- kA1: pack B1h + B2h ----------------
__global__ __launch_bounds__(512) void kA1(
    const float* __restrict__ W1a, const float* __restrict__ W1g,
    const float* __restrict__ W2a, const float* __restrict__ W2g)
{
    int id = blockIdx.x * 512 + threadIdx.x;
    if (id < 8192) {                                  // B1h: B[k][u]=W1[u][64+k]
        int grp = id >> 10, rem = id & 1023;
        int nt = rem >> 5, lane = rem & 31;
        int t = lane & 3, g = lane >> 2;
        int u = nt * 8 + g;
        const float* wr = ((u < 128) ? (W1a + u * 192) : (W1g + (u - 128) * 192)) + 64 + grp * 16;
        g_B1h[id] = make_uint2(packh2(wr[2*t], wr[2*t+1]), packh2(wr[2*t+8], wr[2*t+9]));
    } else if (id < 12288) {                          // B2h: +W2a / -W2g
        int i = id - 8192;
        int grpG = i >> 8, rem = i & 255;
        int nt = rem >> 5, lane = rem & 31;
        int t = lane & 3, g = lane >> 2;
        int o = nt * 8 + g;
        if (grpG < 8) {
            const float* wr = W2a + o * 128 + grpG * 16;
            g_B2h[i] = make_uint2(packh2(wr[2*t], wr[2*t+1]), packh2(wr[2*t+8], wr[2*t+9]));
        } else {
            const float* wr = W2g + o * 128 + (grpG - 8) * 16;
            g_B2h[i] = make_uint2(packh2(-wr[2*t], -wr[2*t+1]), packh2(-wr[2*t+8], -wr[2*t+9]));
        }
    }
}

// ---------------- kA2: pack B3h + B4h ----------------
__global__ __launch_bounds__(512) void kA2(
    const float* __restrict__ Wih, const float* __restrict__ Whh)
{
    int id = blockIdx.x * 512 + threadIdx.x;
    if (id < 12288) {                                 // B3h: Whh[j][k]
        int grp = id / 1536, rem = id % 1536;
        int nt = rem >> 5, lane = rem & 31;
        int t = lane & 3, g = lane >> 2;
        int j = nt * 8 + g;
        const float* wr = Whh + j * 128 + grp * 16;
        g_B3h[id] = make_uint2(packh2(wr[2*t], wr[2*t+1]), packh2(wr[2*t+8], wr[2*t+9]));
    } else if (id < 18432) {                          // B4h: Wih[j][k], k<64
        int i = id - 12288;
        int grp = i / 1536, rem = i % 1536;
        int nt = rem >> 5, lane = rem & 31;
        int t = lane & 3, g = lane >> 2;
        int j = nt * 8 + g;
        const float* wr = Wih + j * 65 + grp * 16;
        g_B4h[i] = make_uint2(packh2(wr[2*t], wr[2*t+1]), packh2(wr[2*t+8], wr[2*t+9]));
    }
}

// ---------------- kA3: misc vectors ----------------
__global__ __launch_bounds__(512) void kA3(
    const float* __restrict__ x,
    const float* __restrict__ W1a, const float* __restrict__ b1a,
    const float* __restrict__ W1g, const float* __restrict__ b1g,
    const float* __restrict__ b2a, const float* __restrict__ b2g,
    const float* __restrict__ Wih,
    const float* __restrict__ bih, const float* __restrict__ bhh)
{
    int id = blockIdx.x * 512 + threadIdx.x;
    if (id < 256) {                                   // xc (exact fp32 x-fold)
        const float* W = (id < 128) ? W1a : W1g;
        const float* b = (id < 128) ? b1a : b1g;
        int j = id & 127;
        float s = b[j];
        const float* row = W + j * 192;
        #pragma unroll 8
        for (int k = 0; k < 64; k++) s += row[k] * x[k];
        g_xc[id] = s;
    } else if (id < 320) {
        int o = id - 256;
        g_b2d[o] = b2a[o] - b2g[o];
    } else if (id < 704) {
        int j = id - 320;
        g_wt[j] = Wih[j * 65 + 64];
    } else if (id < 960) {
        int j = id - 704;
        g_brz[j] = bih[j] + bhh[j];
    } else if (id < 1088) {
        int j = id - 960;
        g_bni[j] = bih[256 + j];
    } else if (id < 1216) {
        int j = id - 1088;
        g_bnh[j] = bhh[256 + j];
    }
}

// ---------------- Kernel B: fused pipeline, 256thr/64cells, 2 blocks/SM ----------------
__global__ __launch_bounds__(TPB, 2) void kB(
    const float* __restrict__ hiddens,
    float* __restrict__ dout)
{
    extern __shared__ float sm[];
    __half* h_h   = (__half*)(sm + OFF_HH);
    __half* c1h   = (__half*)(sm + OFF_C1H);
    float*  nh_s  = sm + OFF_C1H;        // aliases c1h after stage 2
    __half* outh  = (__half*)(sm + OFF_OUTH);
    float*  t_s   = sm + OFF_T;
    float*  e_s   = sm + OFF_E;
    float*  xc_s  = sm + OFF_XC;
    float*  b2d_s = sm + OFF_B2D;
    float*  brz_s = sm + OFF_BRZ;
    float*  bni_s = sm + OFF_BNI;
    float*  bnh_s = sm + OFF_BNH;
    float*  wt_s  = sm + OFF_WT;

    const int tid  = threadIdx.x;
    const int blk  = blockIdx.x;
    const int w    = tid >> 5;            // 0..7
    const int lane = tid & 31;
    const int t4   = lane & 3;
    const int g    = lane >> 2;

    // ldmatrix per-lane byte offsets (row = lane&15, col-half = lane>>4)
    const unsigned sb   = (unsigned)__cvta_generic_to_shared(sm);
    const int lrow = lane & 15, lcol = lane >> 4;
    const unsigned hB   = sb + OFF_HH  * 4 + 2u * (lrow * HHP  + lcol * 8);
    const unsigned c1B  = sb + OFF_C1H * 4 + 2u * (lrow * C1HP + lcol * 8);
    const unsigned oB   = sb + OFF_OUTH* 4 + 2u * (lrow * OHP  + lcol * 8);

    const float* Hg = hiddens + (size_t)blk * MT * 128;

    // ---- stage 0: load h tile (fp16) + constant tables ----
    #pragma unroll
    for (int i = tid; i < MT * 32; i += TPB) {       // 2048 float4
        float4 v = ((const float4*)Hg)[i];
        int c = i >> 5, k = (i & 31) << 2;
        unsigned* q = (unsigned*)(h_h + c * HHP + k);
        q[0] = packh2(v.x, v.y);
        q[1] = packh2(v.z, v.w);
    }
    { xc_s[tid] = g_xc[tid]; brz_s[tid] = g_brz[tid]; }
    if (tid < 64)  { b2d_s[tid] = g_b2d[tid]; }
    if (tid < 128) { bni_s[tid] = g_bni[tid]; bnh_s[tid] = g_bnh[tid]; }
    if (tid < 256) { if (tid < 128) wt_s[tid + 256] = g_wt[tid + 256]; wt_s[tid & 255] = g_wt[tid & 255]; }
    __syncthreads();

    // ---- stage 1: C1[64x256] = relu(h @ B1 + xc); warp owns 4 n-tiles, loops 4 m-tiles ----
    {
        float acc[4][4][4];                          // [mt][nt][c]
        #pragma unroll
        for (int m = 0; m < 4; m++)
            #pragma unroll
            for (int n = 0; n < 4; n++)
                #pragma unroll
                for (int c = 0; c < 4; c++) acc[m][n][c] = 0.f;
        #pragma unroll
        for (int grp = 0; grp < 8; grp++) {
            uint2 bv[4];
            #pragma unroll
            for (int n = 0; n < 4; n++)
                bv[n] = g_B1h[(grp * 32 + 4 * w + n) * 32 + lane];
            #pragma unroll
            for (int m = 0; m < 4; m++) {
                unsigned a0, a1, a2, a3;
                ldsm4(a0, a1, a2, a3, hB + 2u * (m * 16 * HHP + grp * 16));
                #pragma unroll
                for (int n = 0; n < 4; n++)
                    mma16(acc[m][n], a0, a1, a2, a3, bv[n].x, bv[n].y);
            }
        }
        #pragma unroll
        for (int m = 0; m < 4; m++) {
            int r0 = m * 16 + g, r1 = r0 + 8;
            #pragma unroll
            for (int n = 0; n < 4; n++) {
                int cb = (4 * w + n) * 8 + 2 * t4;
                float x0 = xc_s[cb], x1 = xc_s[cb + 1];
                *(unsigned*)(c1h + r0 * C1HP + cb) =
                    packh2(fmaxf(acc[m][n][0] + x0, 0.f), fmaxf(acc[m][n][1] + x1, 0.f));
                *(unsigned*)(c1h + r1 * C1HP + cb) =
                    packh2(fmaxf(acc[m][n][2] + x0, 0.f), fmaxf(acc[m][n][3] + x1, 0.f));
            }
        }
    }
    __syncthreads();

    // ---- stage 2: out[64x64] = C1 @ B2 + b2d; warp = (mt = w&3, ng = w>>2), full K=256 ----
    {
        const int mt = w & 3, ng = w >> 2;
        float acc[4][4];
        #pragma unroll
        for (int n = 0; n < 4; n++)
            #pragma unroll
            for (int c = 0; c < 4; c++) acc[n][c] = 0.f;
        #pragma unroll
        for (int grpG = 0; grpG < 16; grpG++) {
            unsigned a0, a1, a2, a3;
            ldsm4(a0, a1, a2, a3, c1B + 2u * (mt * 16 * C1HP + grpG * 16));
            #pragma unroll
            for (int ni = 0; ni < 4; ni++) {
                uint2 bv = g_B2h[(grpG * 8 + ng * 4 + ni) * 32 + lane];
                mma16(acc[ni], a0, a1, a2, a3, bv.x, bv.y);
            }
        }
        int r0 = mt * 16 + g, r1 = r0 + 8;
        #pragma unroll
        for (int ni = 0; ni < 4; ni++) {
            int o = (ng * 4 + ni) * 8 + 2 * t4;
            float x0 = b2d_s[o], x1 = b2d_s[o + 1];
            *(unsigned*)(outh + r0 * OHP + o) = packh2(acc[ni][0] + x0, acc[ni][1] + x1);
            *(unsigned*)(outh + r1 * OHP + o) = packh2(acc[ni][2] + x0, acc[ni][3] + x1);
        }
    }
    __syncthreads();

    // ---- t/e (tid<64) — overlapped with GRU pass-1 mma of all warps ----
    if (tid < 64) {
        const unsigned* orow = (const unsigned*)(outh + tid * OHP);
        float s = 0.f;
        #pragma unroll
        for (int c = 0; c < 32; c++) {
            float2 f = __half22float2(*(const __half2*)(orow + c));
            s += f.x * f.x + f.y * f.y;
        }
        float tt = s * (1.f / 64.f);
        t_s[tid] = tt;
        e_s[tid] = expf(tt);
    }

    // ---- GRU: warp owns j-tiles {2w, 2w+1} (j in [16w,16w+16)), two m-half passes ----
    #pragma unroll 1
    for (int mh = 0; mh < 2; mh++) {
        float aR[2][2][4], aZ[2][2][4], aNh[2][2][4], aNi[2][2][4];   // [jt][mt][c]
        #pragma unroll
        for (int jt = 0; jt < 2; jt++)
            #pragma unroll
            for (int m = 0; m < 2; m++)
                #pragma unroll
                for (int c = 0; c < 4; c++)
                    { aR[jt][m][c] = 0.f; aZ[jt][m][c] = 0.f; aNh[jt][m][c] = 0.f; aNi[jt][m][c] = 0.f; }

        // h-side (K=128)
        #pragma unroll
        for (int grp = 0; grp < 8; grp++) {
            uint2 bR0 = g_B3h[(grp * 48 + 2 * w)          * 32 + lane];
            uint2 bR1 = g_B3h[(grp * 48 + 2 * w + 1)      * 32 + lane];
            uint2 bZ0 = g_B3h[(grp * 48 + 16 + 2 * w)     * 32 + lane];
            uint2 bZ1 = g_B3h[(grp * 48 + 16 + 2 * w + 1) * 32 + lane];
            uint2 bN0 = g_B3h[(grp * 48 + 32 + 2 * w)     * 32 + lane];
            uint2 bN1 = g_B3h[(grp * 48 + 32 + 2 * w + 1) * 32 + lane];
            #pragma unroll
            for (int mi = 0; mi < 2; mi++) {
                unsigned a0, a1, a2, a3;
                ldsm4(a0, a1, a2, a3, hB + 2u * ((mh * 2 + mi) * 16 * HHP + grp * 16));
                mma16(aR[0][mi],  a0, a1, a2, a3, bR0.x, bR0.y);
                mma16(aR[1][mi],  a0, a1, a2, a3, bR1.x, bR1.y);
                mma16(aZ[0][mi],  a0, a1, a2, a3, bZ0.x, bZ0.y);
                mma16(aZ[1][mi],  a0, a1, a2, a3, bZ1.x, bZ1.y);
                mma16(aNh[0][mi], a0, a1, a2, a3, bN0.x, bN0.y);
                mma16(aNh[1][mi], a0, a1, a2, a3, bN1.x, bN1.y);
            }
        }
        // i-side (K=64): r,z accumulate on; n separate
        #pragma unroll
        for (int grp = 0; grp < 4; grp++) {
            uint2 bR0 = g_B4h[(grp * 48 + 2 * w)          * 32 + lane];
            uint2 bR1 = g_B4h[(grp * 48 + 2 * w + 1)      * 32 + lane];
            uint2 bZ0 = g_B4h[(grp * 48 + 16 + 2 * w)     * 32 + lane];
            uint2 bZ1 = g_B4h[(grp * 48 + 16 + 2 * w + 1) * 32 + lane];
            uint2 bN0 = g_B4h[(grp * 48 + 32 + 2 * w)     * 32 + lane];
            uint2 bN1 = g_B4h[(grp * 48 + 32 + 2 * w + 1) * 32 + lane];
            #pragma unroll
            for (int mi = 0; mi < 2; mi++) {
                unsigned a0, a1, a2, a3;
                ldsm4(a0, a1, a2, a3, oB + 2u * ((mh * 2 + mi) * 16 * OHP + grp * 16));
                mma16(aR[0][mi],  a0, a1, a2, a3, bR0.x, bR0.y);
                mma16(aR[1][mi],  a0, a1, a2, a3, bR1.x, bR1.y);
                mma16(aZ[0][mi],  a0, a1, a2, a3, bZ0.x, bZ0.y);
                mma16(aZ[1][mi],  a0, a1, a2, a3, bZ1.x, bZ1.y);
                mma16(aNi[0][mi], a0, a1, a2, a3, bN0.x, bN0.y);
                mma16(aNi[1][mi], a0, a1, a2, a3, bN1.x, bN1.y);
            }
        }

        if (mh == 0) __syncthreads();   // t_s/e_s ready; stage-2 c1h reads complete -> nh alias safe

        // epilogue: nh into staging (c1h alias); exact fp32 h re-read from global (L2-hot)
        #pragma unroll
        for (int jt = 0; jt < 2; jt++) {
            int j0 = 16 * w + jt * 8 + 2 * t4;
            float brzr0 = brz_s[j0],       brzr1 = brz_s[j0 + 1];
            float brzz0 = brz_s[128 + j0], brzz1 = brz_s[128 + j0 + 1];
            float bni0  = bni_s[j0],       bni1  = bni_s[j0 + 1];
            float bnh0  = bnh_s[j0],       bnh1  = bnh_s[j0 + 1];
            float wtr0 = wt_s[j0],        wtr1 = wt_s[j0 + 1];
            float wtz0 = wt_s[128 + j0],  wtz1 = wt_s[128 + j0 + 1];
            float wtn0 = wt_s[256 + j0],  wtn1 = wt_s[256 + j0 + 1];
            #pragma unroll
            for (int mi = 0; mi < 2; mi++) {
                int r0 = (mh * 2 + mi) * 16 + g, r1 = r0 + 8;
                float tv0 = t_s[r0], tv1 = t_s[r1];
                float2 hv0 = *(const float2*)(Hg + r0 * 128 + j0);
                float2 hv1 = *(const float2*)(Hg + r1 * 128 + j0);
                {
                    float r = sigmoid_f(aR[jt][mi][0] + brzr0 + tv0 * wtr0);
                    float z = sigmoid_f(aZ[jt][mi][0] + brzz0 + tv0 * wtz0);
                    float n = tanhf(aNi[jt][mi][0] + tv0 * wtn0 + bni0 + r * (aNh[jt][mi][0] + bnh0));
                    nh_s[r0 * NHP + j0] = (1.f - z) * n + z * hv0.x;
                }
                {
                    float r = sigmoid_f(aR[jt][mi][1] + brzr1 + tv0 * wtr1);
                    float z = sigmoid_f(aZ[jt][mi][1] + brzz1 + tv0 * wtz1);
                    float n = tanhf(aNi[jt][mi][1] + tv0 * wtn1 + bni1 + r * (aNh[jt][mi][1] + bnh1));
                    nh_s[r0 * NHP + j0 + 1] = (1.f - z) * n + z * hv0.y;
                }
                {
                    float r = sigmoid_f(aR[jt][mi][2] + brzr0 + tv1 * wtr0);
                    float z = sigmoid_f(aZ[jt][mi][2] + brzz0 + tv1 * wtz0);
                    float n = tanhf(aNi[jt][mi][2] + tv1 * wtn0 + bni0 + r * (aNh[jt][mi][2] + bnh0));
                    nh_s[r1 * NHP + j0] = (1.f - z) * n + z * hv1.x;
                }
                {
                    float r = sigmoid_f(aR[jt][mi][3] + brzr1 + tv1 * wtr1);
                    float z = sigmoid_f(aZ[jt][mi][3] + brzz1 + tv1 * wtz1);
                    float n = tanhf(aNi[jt][mi][3] + tv1 * wtn1 + bni1 + r * (aNh[jt][mi][3] + bnh1));
                    nh_s[r1 * NHP + j0 + 1] = (1.f - z) * n + z * hv1.y;
                }
            }
        }
    }
    __syncthreads();

    // ---- store new_h (pre-sync) coalesced; block partials ----
    float* NH = dout + 65 + (size_t)blk * MT * 128;
    #pragma unroll
    for (int i = tid; i < MT * 128; i += TPB) {
        int c = i >> 7, k = i & 127;
        NH[i] = nh_s[c * NHP + k];
    }
    if (tid < 128) {
        float s = 0.f;
        #pragma unroll 8
        for (int c = 0; c < MT; c++) s += nh_s[c * NHP + tid];
        g_blk_h[(size_t)blk * 128 + tid] = s;
    }
    if (tid < 64) {
        float s = 0.f;
        #pragma unroll 8
        for (int c = 0; c < MT; c++) s += e_s[c] * __half2float(outh[c * OHP + tid]);
        g_blk_wout[(size_t)blk * 64 + tid] = s;
    } else if (tid == 64) {
        float s = 0.f;
        for (int c = 0; c < MT; c++) s += t_s[c];
        g_blk_t[blk] = s;
    } else if (tid == 96) {
        float s = 0.f;
        for (int c = 0; c < MT; c++) s += e_s[c];
        g_blk_e[blk] = s;
    }
}

// ---------------- Kernel C: global reductions + head ----------------
__global__ __launch_bounds__(1024) void kC(
    const float* __restrict__ Wo, const float* __restrict__ bo,
    float* __restrict__ dout)
{
    __shared__ float s_red[1024];
    __shared__ float s_red2[1024];
    __shared__ float s_comb[64];
    __shared__ float s_esum;
    const int tid = threadIdx.x;

    // faction sums: thread = (faction f, hidden j); 256 blocks per faction
    {
        int f = tid >> 7, j = tid & 127;
        const float* p = g_blk_h + (size_t)(f * 256) * 128 + j;
        float s = 0.f;
        #pragma unroll 8
        for (int b = 0; b < 256; b++) s += p[b * 128];
        g_fm[f * 128 + j] = s * (1.f / 16384.f);
        s_red[tid] = s;
    }
    __syncthreads();
    if (tid < 128) {
        float gg = 0.f;
        #pragma unroll
        for (int f = 0; f < 8; f++) gg += s_red[f * 128 + tid];
        g_go[tid] = gg * (1.f / (float)NCELLS);
    }
    __syncthreads();

    // weighted-out numerator: 16 chunks x 64 outputs, 128 blocks/chunk
    {
        int o = tid & 63, ch = tid >> 6;
        const float* p = g_blk_wout + (size_t)(ch * 128) * 64 + o;
        float s = 0.f;
        #pragma unroll 8
        for (int b = 0; b < 128; b++) s += p[b * 64];
        s_red[tid] = s;
    }
    __syncthreads();
    if (tid < 64) {
        float s = 0.f;
        #pragma unroll
        for (int ch = 0; ch < 16; ch++) s += s_red[ch * 64 + tid];
        s_comb[tid] = s;
    }
    __syncthreads();

    // exp-sum + t-sum (2 elements per thread, NBLK==2048)
    float se = 0.f, st = 0.f;
    #pragma unroll
    for (int i = tid; i < NBLK; i += 1024) { se += g_blk_e[i]; st += g_blk_t[i]; }
    s_red[tid]  = se;
    s_red2[tid] = st;
    __syncthreads();
    for (int off = 512; off > 0; off >>= 1) {
        if (tid < off) { s_red[tid] += s_red[tid + off]; s_red2[tid] += s_red2[tid + off]; }
        __syncthreads();
    }
    if (tid == 0) {
        s_esum = s_red[0];
        dout[64] = s_red2[0] * (1.f / (float)NCELLS);
    }
    __syncthreads();

    if (tid < 64) s_comb[tid] *= (1.f / s_esum);
    __syncthreads();
    if (tid < 64) {
        float p = bo[tid];
        const float* wr = Wo + tid * 64;
        #pragma unroll 8
        for (int o = 0; o < 64; o++) p += wr[o] * s_comb[o];
        dout[tid] = p;
    }
}

// ---------------- Kernel D: faction sync, float4 RMW with scalar peel ----------------
// nh = dout+65; nh+3 is 16B-aligned. Chunks cover e in [3, 16777215); peel e=0,1,2 and e=16777215.
__global__ __launch_bounds__(512) void kD(float* __restrict__ nh, const void* __restrict__ stepPtr)
{
    int iv = *(const int*)stepPtr;
    int step = (iv >= 0 && iv < 1000000) ? iv : (int)(*(const float*)stepPtr);
    const bool debate = (step > 5);

    if (blockIdx.x == 0 && threadIdx.x < 4) {
        unsigned e = (threadIdx.x < 3) ? threadIdx.x : 16777215u;
        unsigned cell = e >> 7, j = e & 127u;
        unsigned f = cell >> 14, pos = cell & 16383u;
        float v = nh[e];
        v = 0.85f * v + 0.15f * g_fm[f * 128 + j];
        if (debate && pos < 4096u) v = 0.85f * v + 0.15f * g_go[j];
        nh[e] = v;
    }

    float4* nh4 = (float4*)(nh + 3);
    unsigned base = blockIdx.x * 512u + threadIdx.x;
    const unsigned stride = 2048u * 512u;
    #pragma unroll
    for (int r = 0; r < 4; r++) {
        unsigned q = base + (unsigned)r * stride;
        if (q < 4194303u) {
            float4 v = nh4[q];
            float va[4] = {v.x, v.y, v.z, v.w};
            unsigned e0 = 3u + 4u * q;
            #pragma unroll
            for (int i = 0; i < 4; i++) {
                unsigned e = e0 + (unsigned)i;
                unsigned cell = e >> 7, j = e & 127u;
                unsigned f = cell >> 14, pos = cell & 16383u;
                float val = va[i];
                val = 0.85f * val + 0.15f * g_fm[f * 128 + j];
                if (debate && pos < 4096u) val = 0.85f * val + 0.15f * g_go[j];
                va[i] = val;
            }
            nh4[q] = make_float4(va[0], va[1], va[2], va[3]);
        }
    }
}

// ---------------- launcher ----------------
extern "C" void kernel_launch(void* const* d_in, const int* in_sizes, int n_in,
                              void* d_out, int out_size)
{
    const float* x    = (const float*)d_in[0];
    const float* hid  = (const float*)d_in[1];
    const float* W1a  = (const float*)d_in[2];
    const float* b1a  = (const float*)d_in[3];
    const float* W2a  = (const float*)d_in[4];
    const float* b2a  = (const float*)d_in[5];
    const float* W1g  = (const float*)d_in[6];
    const float* b1g  = (const float*)d_in[7];
    const float* W2g  = (const float*)d_in[8];
    const float* b2g  = (const float*)d_in[9];
    const float* Wih  = (const float*)d_in[10];
    const float* Whh  = (const float*)d_in[11];
    const float* bih  = (const float*)d_in[12];
    const float* bhh  = (const float*)d_in[13];
    const float* Wo   = (const float*)d_in[14];
    const float* bo   = (const float*)d_in[15];
    const void*  step = (n_in > 16) ? (const void*)d_in[16] : (const void*)d_in[15];

    float* out = (float*)d_out;
    float* nh  = out + 65;

    cudaFuncSetAttribute(kB, cudaFuncAttributeMaxDynamicSharedMemorySize, SMEM_KB_BYTES);

    kA1<<<24, 512>>>(W1a, W1g, W2a, W2g);
    kA2<<<36, 512>>>(Wih, Whh);
    kA3<<<3, 512>>>(x, W1a, b1a, W1g, b1g, b2a, b2g, Wih, bih, bhh);
    kB<<<NBLK, TPB, SMEM_KB_BYTES>>>(hid, out);
    kC<<<1, 1024>>>(Wo, bo, out);
    kD<<<2048, 512>>>(nh, step);
}

// round 12
// speedup vs baseline: 8.2289x; 1.0510x over previous
#include <cuda_runtime.h>
#include <cuda_fp16.h>
#include <stdint.h>
#include <math.h>

// ---------------- problem constants ----------------
#define NCELLS 131072
#define MT   64
#define TPB  256
#define NBLK (NCELLS / MT)   // 2048

// ---------------- smem layout (float offsets) ----------------
// all half pitches are ≡ 16 (mod 128) BYTES -> ldmatrix 8-row groups conflict-free
#define HHP   136            // h_h half pitch   (272 B)
#define C1HP  264            // C1h half pitch   (528 B)
#define OHP   72             // out_h half pitch (144 B)
#define NHP   132            // nh fp32 pitch (aliases C1 region exactly: 64*132 = 64*264/2)

#define OFF_HH   0                        // 64*136 h = 4352 floats
#define OFF_C1H  4352                     // 64*264 h = 8448 floats (nh fp32 alias 64*132)
#define OFF_OUTH 12800                    // 64*72 h  = 2304 floats
#define OFF_T    15104                    // 64
#define OFF_E    15168                    // 64
#define OFF_XC   15232                    // 256
#define OFF_B2D  15488                    // 64
#define OFF_BRZ  15552                    // 256
#define OFF_BNI  15808                    // 128
#define OFF_BNH  15936                    // 128
#define OFF_WT   16064                    // 384
#define SMEM_KB_FLOATS 16448
#define SMEM_KB_BYTES  (SMEM_KB_FLOATS * 4)   // 65792 B -> 3 blocks/SM (197 KB)

// ---------------- device scratch (static, allocation-free) ----------------
__device__ uint2 g_B1h[8 * 32 * 32];     // stage1  K=128,N=256
__device__ uint2 g_B2h[16 * 8 * 32];     // stage2  K=256,N=64 (sign-folded)
__device__ uint2 g_B3h[8 * 48 * 32];     // GRU Whh K=128,N=384
__device__ uint2 g_B4h[4 * 48 * 32];     // GRU Wih K=64, N=384
__device__ float g_xc[256];
__device__ float g_b2d[64];
__device__ float g_brz[256];
__device__ float g_bni[128];
__device__ float g_bnh[128];
__device__ float g_wt[384];
__device__ float g_blk_t[NBLK];
__device__ float g_blk_e[NBLK];
__device__ float g_blk_wout[NBLK * 64];
__device__ float g_blk_h[NBLK * 128];
__device__ float g_fm[8 * 128];
__device__ float g_go[128];

// ---------------- helpers ----------------
__device__ __forceinline__ unsigned packh2(float lo, float hi) {
    __half2 h = __floats2half2_rn(lo, hi);
    return *(unsigned*)&h;
}
__device__ __forceinline__ void mma16(float* c,
    unsigned a0, unsigned a1, unsigned a2, unsigned a3,
    unsigned b0, unsigned b1)
{
    asm volatile(
        "mma.sync.aligned.m16n8k16.row.col.f32.f16.f16.f32 "
        "{%0,%1,%2,%3},{%4,%5,%6,%7},{%8,%9},{%0,%1,%2,%3};"
        : "+f"(c[0]), "+f"(c[1]), "+f"(c[2]), "+f"(c[3])
        : "r"(a0), "r"(a1), "r"(a2), "r"(a3), "r"(b0), "r"(b1));
}
__device__ __forceinline__ void ldsm4(unsigned& a0, unsigned& a1, unsigned& a2, unsigned& a3,
                                      unsigned addr)
{
    asm volatile("ldmatrix.sync.aligned.m8n8.x4.shared.b16 {%0,%1,%2,%3}, [%4];"
                 : "=r"(a0), "=r"(a1), "=r"(a2), "=r"(a3) : "r"(addr));
}
__device__ __forceinline__ float sigmoid_f(float x) {
    return 1.f / (1.f + __expf(-x));
}

// ---------------- kA1: pack B1h + B2h ----------------
__global__ __launch_bounds__(512) void kA1(
    const float* __restrict__ W1a, const float* __restrict__ W1g,
    const float* __restrict__ W2a, const float* __restrict__ W2g)
{
    int id = blockIdx.x * 512 + threadIdx.x;
    if (id < 8192) {                                  // B1h: B[k][u]=W1[u][64+k]
        int grp = id >> 10, rem = id & 1023;
        int nt = rem >> 5, lane = rem & 31;
        int t = lane & 3, g = lane >> 2;
        int u = nt * 8 + g;
        const float* wr = ((u < 128) ? (W1a + u * 192) : (W1g + (u - 128) * 192)) + 64 + grp * 16;
        g_B1h[id] = make_uint2(packh2(wr[2*t], wr[2*t+1]), packh2(wr[2*t+8], wr[2*t+9]));
    } else if (id < 12288) {                          // B2h: +W2a / -W2g
        int i = id - 8192;
        int grpG = i >> 8, rem = i & 255;
        int nt = rem >> 5, lane = rem & 31;
        int t = lane & 3, g = lane >> 2;
        int o = nt * 8 + g;
        if (grpG < 8) {
            const float* wr = W2a + o * 128 + grpG * 16;
            g_B2h[i] = make_uint2(packh2(wr[2*t], wr[2*t+1]), packh2(wr[2*t+8], wr[2*t+9]));
        } else {
            const float* wr = W2g + o * 128 + (grpG - 8) * 16;
            g_B2h[i] = make_uint2(packh2(-wr[2*t], -wr[2*t+1]), packh2(-wr[2*t+8], -wr[2*t+9]));
        }
    }
}

// ---------------- kA2: pack B3h + B4h ----------------
__global__ __launch_bounds__(512) void kA2(
    const float* __restrict__ Wih, const float* __restrict__ Whh)
{
    int id = blockIdx.x * 512 + threadIdx.x;
    if (id < 12288) {                                 // B3h: Whh[j][k]
        int grp = id / 1536, rem = id % 1536;
        int nt = rem >> 5, lane = rem & 31;
        int t = lane & 3, g = lane >> 2;
        int j = nt * 8 + g;
        const float* wr = Whh + j * 128 + grp * 16;
        g_B3h[id] = make_uint2(packh2(wr[2*t], wr[2*t+1]), packh2(wr[2*t+8], wr[2*t+9]));
    } else if (id < 18432) {                          // B4h: Wih[j][k], k<64
        int i = id - 12288;
        int grp = i / 1536, rem = i % 1536;
        int nt = rem >> 5, lane = rem & 31;
        int t = lane & 3, g = lane >> 2;
        int j = nt * 8 + g;
        const float* wr = Wih + j * 65 + grp * 16;
        g_B4h[i] = make_uint2(packh2(wr[2*t], wr[2*t+1]), packh2(wr[2*t+8], wr[2*t+9]));
    }
}

// ---------------- kA3: misc vectors ----------------
__global__ __launch_bounds__(512) void kA3(
    const float* __restrict__ x,
    const float* __restrict__ W1a, const float* __restrict__ b1a,
    const float* __restrict__ W1g, const float* __restrict__ b1g,
    const float* __restrict__ b2a, const float* __restrict__ b2g,
    const float* __restrict__ Wih,
    const float* __restrict__ bih, const float* __restrict__ bhh)
{
    int id = blockIdx.x * 512 + threadIdx.x;
    if (id < 256) {                                   // xc (exact fp32 x-fold)
        const float* W = (id < 128) ? W1a : W1g;
        const float* b = (id < 128) ? b1a : b1g;
        int j = id & 127;
        float s = b[j];
        const float* row = W + j * 192;
        #pragma unroll 8
        for (int k = 0; k < 64; k++) s += row[k] * x[k];
        g_xc[id] = s;
    } else if (id < 320) {
        int o = id - 256;
        g_b2d[o] = b2a[o] - b2g[o];
    } else if (id < 704) {
        int j = id - 320;
        g_wt[j] = Wih[j * 65 + 64];
    } else if (id < 960) {
        int j = id - 704;
        g_brz[j] = bih[j] + bhh[j];
    } else if (id < 1088) {
        int j = id - 960;
        g_bni[j] = bih[256 + j];
    } else if (id < 1216) {
        int j = id - 1088;
        g_bnh[j] = bhh[256 + j];
    }
}

// ---------------- Kernel B: fused pipeline, 256thr/64cells, 3 blocks/SM ----------------
__global__ __launch_bounds__(TPB, 3) void kB(
    const float* __restrict__ hiddens,
    float* __restrict__ dout)
{
    extern __shared__ float sm[];
    __half* h_h   = (__half*)(sm + OFF_HH);
    __half* c1h   = (__half*)(sm + OFF_C1H);
    float*  nh_s  = sm + OFF_C1H;        // aliases c1h after stage 2
    __half* outh  = (__half*)(sm + OFF_OUTH);
    float*  t_s   = sm + OFF_T;
    float*  e_s   = sm + OFF_E;
    float*  xc_s  = sm + OFF_XC;
    float*  b2d_s = sm + OFF_B2D;
    float*  brz_s = sm + OFF_BRZ;
    float*  bni_s = sm + OFF_BNI;
    float*  bnh_s = sm + OFF_BNH;
    float*  wt_s  = sm + OFF_WT;

    const int tid  = threadIdx.x;
    const int blk  = blockIdx.x;
    const int w    = tid >> 5;            // 0..7
    const int lane = tid & 31;
    const int t4   = lane & 3;
    const int g    = lane >> 2;

    // ldmatrix per-lane byte offsets (row = lane&15, col-half = lane>>4)
    const unsigned sb   = (unsigned)__cvta_generic_to_shared(sm);
    const int lrow = lane & 15, lcol = lane >> 4;
    const unsigned hB   = sb + OFF_HH  * 4 + 2u * (lrow * HHP  + lcol * 8);
    const unsigned c1B  = sb + OFF_C1H * 4 + 2u * (lrow * C1HP + lcol * 8);
    const unsigned oB   = sb + OFF_OUTH* 4 + 2u * (lrow * OHP  + lcol * 8);

    const float* Hg = hiddens + (size_t)blk * MT * 128;

    // ---- stage 0: load h tile (fp16) + constant tables ----
    #pragma unroll
    for (int i = tid; i < MT * 32; i += TPB) {       // 2048 float4
        float4 v = ((const float4*)Hg)[i];
        int c = i >> 5, k = (i & 31) << 2;
        unsigned* q = (unsigned*)(h_h + c * HHP + k);
        q[0] = packh2(v.x, v.y);
        q[1] = packh2(v.z, v.w);
    }
    { xc_s[tid] = g_xc[tid]; brz_s[tid] = g_brz[tid]; }
    if (tid < 64)  { b2d_s[tid] = g_b2d[tid]; }
    if (tid < 128) { bni_s[tid] = g_bni[tid]; bnh_s[tid] = g_bnh[tid]; }
    { if (tid < 128) wt_s[tid + 256] = g_wt[tid + 256]; wt_s[tid] = g_wt[tid]; }
    __syncthreads();

    // ---- stage 1: C1[64x256] = relu(h @ B1 + xc); two n-half passes (32 acc live) ----
    #pragma unroll 1
    for (int nh2 = 0; nh2 < 2; nh2++) {
        float acc[4][2][4];                          // [mt][n][c]
        #pragma unroll
        for (int m = 0; m < 4; m++)
            #pragma unroll
            for (int n = 0; n < 2; n++)
                #pragma unroll
                for (int c = 0; c < 4; c++) acc[m][n][c] = 0.f;
        #pragma unroll
        for (int grp = 0; grp < 8; grp++) {
            uint2 bv0 = g_B1h[(grp * 32 + 4 * w + 2 * nh2)     * 32 + lane];
            uint2 bv1 = g_B1h[(grp * 32 + 4 * w + 2 * nh2 + 1) * 32 + lane];
            #pragma unroll
            for (int m = 0; m < 4; m++) {
                unsigned a0, a1, a2, a3;
                ldsm4(a0, a1, a2, a3, hB + 2u * (m * 16 * HHP + grp * 16));
                mma16(acc[m][0], a0, a1, a2, a3, bv0.x, bv0.y);
                mma16(acc[m][1], a0, a1, a2, a3, bv1.x, bv1.y);
            }
        }
        #pragma unroll
        for (int m = 0; m < 4; m++) {
            int r0 = m * 16 + g, r1 = r0 + 8;
            #pragma unroll
            for (int n = 0; n < 2; n++) {
                int cb = (4 * w + 2 * nh2 + n) * 8 + 2 * t4;
                float x0 = xc_s[cb], x1 = xc_s[cb + 1];
                *(unsigned*)(c1h + r0 * C1HP + cb) =
                    packh2(fmaxf(acc[m][n][0] + x0, 0.f), fmaxf(acc[m][n][1] + x1, 0.f));
                *(unsigned*)(c1h + r1 * C1HP + cb) =
                    packh2(fmaxf(acc[m][n][2] + x0, 0.f), fmaxf(acc[m][n][3] + x1, 0.f));
            }
        }
    }
    __syncthreads();

    // ---- stage 2: out[64x64] = C1 @ B2 + b2d; warp = (mt = w&3, ng = w>>2), full K=256 ----
    {
        const int mt = w & 3, ng = w >> 2;
        float acc[4][4];
        #pragma unroll
        for (int n = 0; n < 4; n++)
            #pragma unroll
            for (int c = 0; c < 4; c++) acc[n][c] = 0.f;
        #pragma unroll
        for (int grpG = 0; grpG < 16; grpG++) {
            unsigned a0, a1, a2, a3;
            ldsm4(a0, a1, a2, a3, c1B + 2u * (mt * 16 * C1HP + grpG * 16));
            #pragma unroll
            for (int ni = 0; ni < 4; ni++) {
                uint2 bv = g_B2h[(grpG * 8 + ng * 4 + ni) * 32 + lane];
                mma16(acc[ni], a0, a1, a2, a3, bv.x, bv.y);
            }
        }
        int r0 = mt * 16 + g, r1 = r0 + 8;
        #pragma unroll
        for (int ni = 0; ni < 4; ni++) {
            int o = (ng * 4 + ni) * 8 + 2 * t4;
            float x0 = b2d_s[o], x1 = b2d_s[o + 1];
            *(unsigned*)(outh + r0 * OHP + o) = packh2(acc[ni][0] + x0, acc[ni][1] + x1);
            *(unsigned*)(outh + r1 * OHP + o) = packh2(acc[ni][2] + x0, acc[ni][3] + x1);
        }
    }
    __syncthreads();

    // ---- t/e (tid<64) — overlapped with GRU pass-0 mma of all warps ----
    if (tid < 64) {
        const unsigned* orow = (const unsigned*)(outh + tid * OHP);
        float s = 0.f;
        #pragma unroll
        for (int c = 0; c < 32; c++) {
            float2 f = __half22float2(*(const __half2*)(orow + c));
            s += f.x * f.x + f.y * f.y;
        }
        float tt = s * (1.f / 64.f);
        t_s[tid] = tt;
        e_s[tid] = expf(tt);
    }

    // ---- GRU: 4 passes (m-half mh, j-tile jt); warp's j-slice = [16w+8jt, 16w+8jt+8) ----
    #pragma unroll 1
    for (int p = 0; p < 4; p++) {
        const int mh = p >> 1, jt = p & 1;
        float aR[2][4], aZ[2][4], aNh[2][4], aNi[2][4];   // [mi][c]  (32 acc live)
        #pragma unroll
        for (int m = 0; m < 2; m++)
            #pragma unroll
            for (int c = 0; c < 4; c++)
                { aR[m][c] = 0.f; aZ[m][c] = 0.f; aNh[m][c] = 0.f; aNi[m][c] = 0.f; }

        // h-side (K=128)
        #pragma unroll
        for (int grp = 0; grp < 8; grp++) {
            uint2 bR = g_B3h[(grp * 48 + 2 * w + jt)      * 32 + lane];
            uint2 bZ = g_B3h[(grp * 48 + 16 + 2 * w + jt) * 32 + lane];
            uint2 bN = g_B3h[(grp * 48 + 32 + 2 * w + jt) * 32 + lane];
            #pragma unroll
            for (int mi = 0; mi < 2; mi++) {
                unsigned a0, a1, a2, a3;
                ldsm4(a0, a1, a2, a3, hB + 2u * ((mh * 2 + mi) * 16 * HHP + grp * 16));
                mma16(aR[mi],  a0, a1, a2, a3, bR.x, bR.y);
                mma16(aZ[mi],  a0, a1, a2, a3, bZ.x, bZ.y);
                mma16(aNh[mi], a0, a1, a2, a3, bN.x, bN.y);
            }
        }
        // i-side (K=64): r,z accumulate on; n separate
        #pragma unroll
        for (int grp = 0; grp < 4; grp++) {
            uint2 bR = g_B4h[(grp * 48 + 2 * w + jt)      * 32 + lane];
            uint2 bZ = g_B4h[(grp * 48 + 16 + 2 * w + jt) * 32 + lane];
            uint2 bN = g_B4h[(grp * 48 + 32 + 2 * w + jt) * 32 + lane];
            #pragma unroll
            for (int mi = 0; mi < 2; mi++) {
                unsigned a0, a1, a2, a3;
                ldsm4(a0, a1, a2, a3, oB + 2u * ((mh * 2 + mi) * 16 * OHP + grp * 16));
                mma16(aR[mi],  a0, a1, a2, a3, bR.x, bR.y);
                mma16(aZ[mi],  a0, a1, a2, a3, bZ.x, bZ.y);
                mma16(aNi[mi], a0, a1, a2, a3, bN.x, bN.y);
            }
        }

        if (p == 0) __syncthreads();   // t_s/e_s ready; stage-2 c1h reads complete -> nh alias safe

        // epilogue: nh into staging (c1h alias); exact fp32 h re-read from global (L2-hot)
        {
            int j0 = 16 * w + jt * 8 + 2 * t4;
            float brzr0 = brz_s[j0],       brzr1 = brz_s[j0 + 1];
            float brzz0 = brz_s[128 + j0], brzz1 = brz_s[128 + j0 + 1];
            float bni0  = bni_s[j0],       bni1  = bni_s[j0 + 1];
            float bnh0  = bnh_s[j0],       bnh1  = bnh_s[j0 + 1];
            float wtr0 = wt_s[j0],        wtr1 = wt_s[j0 + 1];
            float wtz0 = wt_s[128 + j0],  wtz1 = wt_s[128 + j0 + 1];
            float wtn0 = wt_s[256 + j0],  wtn1 = wt_s[256 + j0 + 1];
            #pragma unroll
            for (int mi = 0; mi < 2; mi++) {
                int r0 = (mh * 2 + mi) * 16 + g, r1 = r0 + 8;
                float tv0 = t_s[r0], tv1 = t_s[r1];
                float2 hv0 = *(const float2*)(Hg + r0 * 128 + j0);
                float2 hv1 = *(const float2*)(Hg + r1 * 128 + j0);
                {
                    float r = sigmoid_f(aR[mi][0] + brzr0 + tv0 * wtr0);
                    float z = sigmoid_f(aZ[mi][0] + brzz0 + tv0 * wtz0);
                    float n = tanhf(aNi[mi][0] + tv0 * wtn0 + bni0 + r * (aNh[mi][0] + bnh0));
                    nh_s[r0 * NHP + j0] = (1.f - z) * n + z * hv0.x;
                }
                {
                    float r = sigmoid_f(aR[mi][1] + brzr1 + tv0 * wtr1);
                    float z = sigmoid_f(aZ[mi][1] + brzz1 + tv0 * wtz1);
                    float n = tanhf(aNi[mi][1] + tv0 * wtn1 + bni1 + r * (aNh[mi][1] + bnh1));
                    nh_s[r0 * NHP + j0 + 1] = (1.f - z) * n + z * hv0.y;
                }
                {
                    float r = sigmoid_f(aR[mi][2] + brzr0 + tv1 * wtr0);
                    float z = sigmoid_f(aZ[mi][2] + brzz0 + tv1 * wtz0);
                    float n = tanhf(aNi[mi][2] + tv1 * wtn0 + bni0 + r * (aNh[mi][2] + bnh0));
                    nh_s[r1 * NHP + j0] = (1.f - z) * n + z * hv1.x;
                }
                {
                    float r = sigmoid_f(aR[mi][3] + brzr1 + tv1 * wtr1);
                    float z = sigmoid_f(aZ[mi][3] + brzz1 + tv1 * wtz1);
                    float n = tanhf(aNi[mi][3] + tv1 * wtn1 + bni1 + r * (aNh[mi][3] + bnh1));
                    nh_s[r1 * NHP + j0 + 1] = (1.f - z) * n + z * hv1.y;
                }
            }
        }
    }
    __syncthreads();

    // ---- store new_h (pre-sync) coalesced; block partials ----
    float* NH = dout + 65 + (size_t)blk * MT * 128;
    #pragma unroll
    for (int i = tid; i < MT * 128; i += TPB) {
        int c = i >> 7, k = i & 127;
        NH[i] = nh_s[c * NHP + k];
    }
    if (tid < 128) {
        float s = 0.f;
        #pragma unroll 8
        for (int c = 0; c < MT; c++) s += nh_s[c * NHP + tid];
        g_blk_h[(size_t)blk * 128 + tid] = s;
    }
    if (tid < 64) {
        float s = 0.f;
        #pragma unroll 8
        for (int c = 0; c < MT; c++) s += e_s[c] * __half2float(outh[c * OHP + tid]);
        g_blk_wout[(size_t)blk * 64 + tid] = s;
    } else if (tid == 64) {
        float s = 0.f;
        for (int c = 0; c < MT; c++) s += t_s[c];
        g_blk_t[blk] = s;
    } else if (tid == 96) {
        float s = 0.f;
        for (int c = 0; c < MT; c++) s += e_s[c];
        g_blk_e[blk] = s;
    }
}

// ---------------- Kernel C: global reductions + head ----------------
__global__ __launch_bounds__(1024) void kC(
    const float* __restrict__ Wo, const float* __restrict__ bo,
    float* __restrict__ dout)
{
    __shared__ float s_red[1024];
    __shared__ float s_red2[1024];
    __shared__ float s_comb[64];
    __shared__ float s_esum;
    const int tid = threadIdx.x;

    // faction sums: thread = (faction f, hidden j); 256 blocks per faction
    {
        int f = tid >> 7, j = tid & 127;
        const float* p = g_blk_h + (size_t)(f * 256) * 128 + j;
        float s = 0.f;
        #pragma unroll 8
        for (int b = 0; b < 256; b++) s += p[b * 128];
        g_fm[f * 128 + j] = s * (1.f / 16384.f);
        s_red[tid] = s;
    }
    __syncthreads();
    if (tid < 128) {
        float gg = 0.f;
        #pragma unroll
        for (int f = 0; f < 8; f++) gg += s_red[f * 128 + tid];
        g_go[tid] = gg * (1.f / (float)NCELLS);
    }
    __syncthreads();

    // weighted-out numerator: 16 chunks x 64 outputs, 128 blocks/chunk
    {
        int o = tid & 63, ch = tid >> 6;
        const float* p = g_blk_wout + (size_t)(ch * 128) * 64 + o;
        float s = 0.f;
        #pragma unroll 8
        for (int b = 0; b < 128; b++) s += p[b * 64];
        s_red[tid] = s;
    }
    __syncthreads();
    if (tid < 64) {
        float s = 0.f;
        #pragma unroll
        for (int ch = 0; ch < 16; ch++) s += s_red[ch * 64 + tid];
        s_comb[tid] = s;
    }
    __syncthreads();

    // exp-sum + t-sum (2 elements per thread, NBLK==2048)
    float se = 0.f, st = 0.f;
    #pragma unroll
    for (int i = tid; i < NBLK; i += 1024) { se += g_blk_e[i]; st += g_blk_t[i]; }
    s_red[tid]  = se;
    s_red2[tid] = st;
    __syncthreads();
    for (int off = 512; off > 0; off >>= 1) {
        if (tid < off) { s_red[tid] += s_red[tid + off]; s_red2[tid] += s_red2[tid + off]; }
        __syncthreads();
    }
    if (tid == 0) {
        s_esum = s_red[0];
        dout[64] = s_red2[0] * (1.f / (float)NCELLS);
    }
    __syncthreads();

    if (tid < 64) s_comb[tid] *= (1.f / s_esum);
    __syncthreads();
    if (tid < 64) {
        float p = bo[tid];
        const float* wr = Wo + tid * 64;
        #pragma unroll 8
        for (int o = 0; o < 64; o++) p += wr[o] * s_comb[o];
        dout[tid] = p;
    }
}

// ---------------- Kernel D: faction sync, float4 RMW with scalar peel ----------------
// nh = dout+65; nh+3 is 16B-aligned. Chunks cover e in [3, 16777215); peel e=0,1,2 and e=16777215.
__global__ __launch_bounds__(512) void kD(float* __restrict__ nh, const void* __restrict__ stepPtr)
{
    int iv = *(const int*)stepPtr;
    int step = (iv >= 0 && iv < 1000000) ? iv : (int)(*(const float*)stepPtr);
    const bool debate = (step > 5);

    if (blockIdx.x == 0 && threadIdx.x < 4) {
        unsigned e = (threadIdx.x < 3) ? threadIdx.x : 16777215u;
        unsigned cell = e >> 7, j = e & 127u;
        unsigned f = cell >> 14, pos = cell & 16383u;
        float v = nh[e];
        v = 0.85f * v + 0.15f * g_fm[f * 128 + j];
        if (debate && pos < 4096u) v = 0.85f * v + 0.15f * g_go[j];
        nh[e] = v;
    }

    float4* nh4 = (float4*)(nh + 3);
    unsigned base = blockIdx.x * 512u + threadIdx.x;
    const unsigned stride = 2048u * 512u;
    #pragma unroll
    for (int r = 0; r < 4; r++) {
        unsigned q = base + (unsigned)r * stride;
        if (q < 4194303u) {
            float4 v = nh4[q];
            float va[4] = {v.x, v.y, v.z, v.w};
            unsigned e0 = 3u + 4u * q;
            #pragma unroll
            for (int i = 0; i < 4; i++) {
                unsigned e = e0 + (unsigned)i;
                unsigned cell = e >> 7, j = e & 127u;
                unsigned f = cell >> 14, pos = cell & 16383u;
                float val = va[i];
                val = 0.85f * val + 0.15f * g_fm[f * 128 + j];
                if (debate && pos < 4096u) val = 0.85f * val + 0.15f * g_go[j];
                va[i] = val;
            }
            nh4[q] = make_float4(va[0], va[1], va[2], va[3]);
        }
    }
}

// ---------------- launcher ----------------
extern "C" void kernel_launch(void* const* d_in, const int* in_sizes, int n_in,
                              void* d_out, int out_size)
{
    const float* x    = (const float*)d_in[0];
    const float* hid  = (const float*)d_in[1];
    const float* W1a  = (const float*)d_in[2];
    const float* b1a  = (const float*)d_in[3];
    const float* W2a  = (const float*)d_in[4];
    const float* b2a  = (const float*)d_in[5];
    const float* W1g  = (const float*)d_in[6];
    const float* b1g  = (const float*)d_in[7];
    const float* W2g  = (const float*)d_in[8];
    const float* b2g  = (const float*)d_in[9];
    const float* Wih  = (const float*)d_in[10];
    const float* Whh  = (const float*)d_in[11];
    const float* bih  = (const float*)d_in[12];
    const float* bhh  = (const float*)d_in[13];
    const float* Wo   = (const float*)d_in[14];
    const float* bo   = (const float*)d_in[15];
    const void*  step = (n_in > 16) ? (const void*)d_in[16] : (const void*)d_in[15];

    float* out = (float*)d_out;
    float* nh  = out + 65;

    cudaFuncSetAttribute(kB, cudaFuncAttributeMaxDynamicSharedMemorySize, SMEM_KB_BYTES);

    kA1<<<24, 512>>>(W1a, W1g, W2a, W2g);
    kA2<<<36, 512>>>(Wih, Whh);
    kA3<<<3, 512>>>(x, W1a, b1a, W1g, b1g, b2a, b2g, Wih, bih, bhh);
    kB<<<NBLK, TPB, SMEM_KB_BYTES>>>(hid, out);
    kC<<<1, 1024>>>(Wo, bo, out);
    kD<<<2048, 512>>>(nh, step);
}